// round 8
// baseline (speedup 1.0000x reference)
#include <cuda_runtime.h>
#include <math_constants.h>
#include <mma.h>
#include <cstdint>

using namespace nvcuda;

#define BATCH  4
#define SEQ    2048
#define DMODEL 1024
#define HDIM   64
#define SCALE  0.03125f   // 1/sqrt(1024)
#define PAD    68         // floats per SMEM row (16B-aligned, conflict-poor)

// ---------------------------------------------------------------------------
// Global scratch (allocation-free rule: __device__ arrays)
// ---------------------------------------------------------------------------
__device__ float g_q[BATCH * SEQ * HDIM];        // projected q (= k = v), fp32
__device__ float g_norm[BATCH * SEQ];            // |q_row|
__device__ float g_bmax[BATCH];                  // max row norm per batch
__device__ float g_Opart[2][BATCH * SEQ * HDIM]; // split-KV partial O (unnormalized)
__device__ float g_lpart[2][BATCH * SEQ];        // split-KV partial l

__device__ __forceinline__ float to_tf32(float x) {
    float y;
    asm("cvt.rna.tf32.f32 %0, %1;" : "=f"(y) : "f"(x));
    return y;
}

// ---------------------------------------------------------------------------
// Projection: q = x · Wq^T  (proven round-4 core) + row norms.
// BM=32, BK=64, 256 threads, grid = 256 CTAs.
// ---------------------------------------------------------------------------
__global__ __launch_bounds__(256) void proj_kernel(const float* __restrict__ x,
                                                   const float* __restrict__ wq)
{
    __shared__ float Xs[32][68];
    __shared__ float Wsm[64][68];

    const int m0  = blockIdx.x * 32;
    const int tid = threadIdx.x;
    const int w   = tid >> 5;
    const int l   = tid & 31;

    float c[4][2] = {};

    for (int kt = 0; kt < DMODEL; kt += 64) {
        __syncthreads();
        #pragma unroll
        for (int u = 0; u < 2; ++u) {
            const int f = u * 256 + tid;
            const int r = f >> 4;
            const int cc = (f & 15) << 2;
            *(float4*)&Xs[r][cc] = *(const float4*)(x + (size_t)(m0 + r) * DMODEL + kt + cc);
        }
        #pragma unroll
        for (int u = 0; u < 4; ++u) {
            const int f = u * 256 + tid;
            const int r = f >> 4;
            const int cc = (f & 15) << 2;
            *(float4*)&Wsm[r][cc] = *(const float4*)(wq + (size_t)r * DMODEL + kt + cc);
        }
        __syncthreads();

        #pragma unroll
        for (int k = 0; k < 64; k += 4) {
            float4 a[4], b[2];
            #pragma unroll
            for (int i = 0; i < 4; ++i) a[i] = *(const float4*)&Xs[4 * w + i][k];
            b[0] = *(const float4*)&Wsm[l][k];
            b[1] = *(const float4*)&Wsm[l + 32][k];
            #pragma unroll
            for (int i = 0; i < 4; ++i) {
                #pragma unroll
                for (int m = 0; m < 2; ++m) {
                    c[i][m] = fmaf(a[i].x, b[m].x, c[i][m]);
                    c[i][m] = fmaf(a[i].y, b[m].y, c[i][m]);
                    c[i][m] = fmaf(a[i].z, b[m].z, c[i][m]);
                    c[i][m] = fmaf(a[i].w, b[m].w, c[i][m]);
                }
            }
        }
    }

    #pragma unroll
    for (int i = 0; i < 4; ++i) {
        const int row = m0 + 4 * w + i;
        g_q[(size_t)row * HDIM + l]      = c[i][0];
        g_q[(size_t)row * HDIM + l + 32] = c[i][1];
        float n2 = c[i][0] * c[i][0] + c[i][1] * c[i][1];
        #pragma unroll
        for (int off = 16; off > 0; off >>= 1)
            n2 += __shfl_xor_sync(0xffffffffu, n2, off);
        if (l == 0) g_norm[row] = sqrtf(n2);
    }
}

// ---------------------------------------------------------------------------
// Per-batch max of row norms.
// ---------------------------------------------------------------------------
__global__ __launch_bounds__(256) void bmax_kernel()
{
    __shared__ float red[8];
    const int b   = blockIdx.x;
    const int tid = threadIdx.x;
    float m = 0.0f;
    for (int i = tid; i < SEQ; i += 256)
        m = fmaxf(m, g_norm[b * SEQ + i]);
    #pragma unroll
    for (int off = 16; off > 0; off >>= 1)
        m = fmaxf(m, __shfl_xor_sync(0xffffffffu, m, off));
    if ((tid & 31) == 0) red[tid >> 5] = m;
    __syncthreads();
    if (tid == 0) {
        float r = red[0];
        #pragma unroll
        for (int i = 1; i < 8; ++i) r = fmaxf(r, red[i]);
        g_bmax[b] = r;
    }
}

// ---------------------------------------------------------------------------
// Tensor-core (wmma tf32, 3xTF32) causal attention with q = k = v.
// CTA: 64 q-rows, KV tiles of 64, 128 threads (4 warps x 16-row strips).
// Static-max softmax: p = exp(s*scale - Mrow); O accumulates in wmma
// accumulator fragments across all tiles (no rescale). Split-KV x2.
// grid = (64, BATCH): qb = 31 - (bx>>1) (heavy first), split = bx&1.
// SMEM regions (floats, each 64xPAD): Qhi Qlo Khi Klo Ps(=Phi) Plo.
// V tile == K tile (row-major B for PV, col-major B for S).
// ---------------------------------------------------------------------------
#define REG (64 * PAD)
#define ATTN_SMEM_BYTES (6 * REG * 4)

__global__ __launch_bounds__(128) void attn_mma_kernel()
{
    extern __shared__ float sm[];
    float* Qhi = sm;
    float* Qlo = sm + REG;
    float* Khi = sm + 2 * REG;
    float* Klo = sm + 3 * REG;
    float* Ps  = sm + 4 * REG;   // S staging, then P hi (in place)
    float* Plo = sm + 5 * REG;

    const int tid   = threadIdx.x;
    const int w     = tid >> 5;
    const int qb    = 31 - ((int)blockIdx.x >> 1);  // heavy row-blocks first
    const int split = blockIdx.x & 1;
    const int batch = blockIdx.y;
    const float* qbase = g_q + (size_t)batch * SEQ * HDIM;

    // ---- prologue: load Q tile (rows qb*64..+63), split to tf32 hi/lo
    #pragma unroll
    for (int u = 0; u < 8; ++u) {
        const int idx = u * 128 + tid;          // float4 index, 0..1023
        const int r   = idx >> 4;
        const int c4  = (idx & 15) << 2;
        float4 v = *(const float4*)(qbase + (size_t)(qb * 64 + r) * HDIM + c4);
        float4 hi, lo;
        hi.x = to_tf32(v.x); lo.x = to_tf32(v.x - hi.x);
        hi.y = to_tf32(v.y); lo.y = to_tf32(v.y - hi.y);
        hi.z = to_tf32(v.z); lo.z = to_tf32(v.z - hi.z);
        hi.w = to_tf32(v.w); lo.w = to_tf32(v.w - hi.w);
        *(float4*)&Qhi[r * PAD + c4] = hi;
        *(float4*)&Qlo[r * PAD + c4] = lo;
    }

    // softmax ownership: thread -> row (tid>>1), column half (tid&1)*32
    const int srow  = tid >> 1;
    const int chalf = (tid & 1) * 32;
    const int row_g = qb * 64 + srow;
    const float Mrow = g_norm[batch * SEQ + row_g] * g_bmax[batch] * SCALE;
    float l_acc = 0.0f;

    wmma::fragment<wmma::accumulator, 16, 16, 8, float> accO[4];
    #pragma unroll
    for (int n = 0; n < 4; ++n) wmma::fill_fragment(accO[n], 0.0f);

    const int nT = qb + 1;
    const int h  = nT >> 1;
    const int k0 = split ? h : 0;
    const int k1 = split ? nT : h;

    for (int kt = k0; kt < k1; ++kt) {
        __syncthreads();   // previous PV done reading Khi/Klo (also covers Q prologue)
        // ---- load K (=V) tile, split tf32 hi/lo
        #pragma unroll
        for (int u = 0; u < 8; ++u) {
            const int idx = u * 128 + tid;
            const int r   = idx >> 4;
            const int c4  = (idx & 15) << 2;
            float4 v = *(const float4*)(qbase + (size_t)(kt * 64 + r) * HDIM + c4);
            float4 hi, lo;
            hi.x = to_tf32(v.x); lo.x = to_tf32(v.x - hi.x);
            hi.y = to_tf32(v.y); lo.y = to_tf32(v.y - hi.y);
            hi.z = to_tf32(v.z); lo.z = to_tf32(v.z - hi.z);
            hi.w = to_tf32(v.w); lo.w = to_tf32(v.w - hi.w);
            *(float4*)&Khi[r * PAD + c4] = hi;
            *(float4*)&Klo[r * PAD + c4] = lo;
        }
        __syncthreads();

        // ---- S = Q · K^T  (3xTF32), per-warp 16x64 strip
        {
            wmma::fragment<wmma::accumulator, 16, 16, 8, float> accS[4];
            #pragma unroll
            for (int n = 0; n < 4; ++n) wmma::fill_fragment(accS[n], 0.0f);

            wmma::fragment<wmma::matrix_a, 16, 16, 8, wmma::precision::tf32, wmma::row_major> ah, al;
            wmma::fragment<wmma::matrix_b, 16, 16, 8, wmma::precision::tf32, wmma::col_major> bh, bl;

            #pragma unroll
            for (int ks = 0; ks < 8; ++ks) {
                wmma::load_matrix_sync(ah, Qhi + w * 16 * PAD + ks * 8, PAD);
                wmma::load_matrix_sync(al, Qlo + w * 16 * PAD + ks * 8, PAD);
                #pragma unroll
                for (int n = 0; n < 4; ++n) {
                    wmma::load_matrix_sync(bh, Khi + n * 16 * PAD + ks * 8, PAD);
                    wmma::load_matrix_sync(bl, Klo + n * 16 * PAD + ks * 8, PAD);
                    wmma::mma_sync(accS[n], ah, bh, accS[n]);
                    wmma::mma_sync(accS[n], ah, bl, accS[n]);
                    wmma::mma_sync(accS[n], al, bh, accS[n]);
                }
            }
            #pragma unroll
            for (int n = 0; n < 4; ++n)
                wmma::store_matrix_sync(Ps + w * 16 * PAD + n * 16, accS[n], PAD,
                                        wmma::mem_row_major);
        }
        __syncthreads();

        // ---- softmax (static max): p = exp(s*scale - Mrow), causal mask
        #pragma unroll
        for (int j = 0; j < 8; ++j) {
            const int c = chalf + j * 4;
            float4 s4 = *(const float4*)&Ps[srow * PAD + c];
            float p[4] = {s4.x, s4.y, s4.z, s4.w};
            float4 hi, lo;
            float ph[4], pl[4];
            #pragma unroll
            for (int e = 0; e < 4; ++e) {
                const int col_g = kt * 64 + c + e;
                float pe = __expf(fmaf(p[e], SCALE, -Mrow));
                pe = (col_g > row_g) ? 0.0f : pe;
                l_acc += pe;
                ph[e] = to_tf32(pe);
                pl[e] = to_tf32(pe - ph[e]);
            }
            hi.x = ph[0]; hi.y = ph[1]; hi.z = ph[2]; hi.w = ph[3];
            lo.x = pl[0]; lo.y = pl[1]; lo.z = pl[2]; lo.w = pl[3];
            *(float4*)&Ps[srow * PAD + c]  = hi;
            *(float4*)&Plo[srow * PAD + c] = lo;
        }
        __syncthreads();

        // ---- O += P · V  (V == K tile, row-major B), 3xTF32
        {
            wmma::fragment<wmma::matrix_a, 16, 16, 8, wmma::precision::tf32, wmma::row_major> ph, pl;
            wmma::fragment<wmma::matrix_b, 16, 16, 8, wmma::precision::tf32, wmma::row_major> vh, vl;
            #pragma unroll
            for (int ks = 0; ks < 8; ++ks) {
                wmma::load_matrix_sync(ph, Ps  + w * 16 * PAD + ks * 8, PAD);
                wmma::load_matrix_sync(pl, Plo + w * 16 * PAD + ks * 8, PAD);
                #pragma unroll
                for (int n = 0; n < 4; ++n) {
                    wmma::load_matrix_sync(vh, Khi + (ks * 8) * PAD + n * 16, PAD);
                    wmma::load_matrix_sync(vl, Klo + (ks * 8) * PAD + n * 16, PAD);
                    wmma::mma_sync(accO[n], ph, vh, accO[n]);
                    wmma::mma_sync(accO[n], ph, vl, accO[n]);
                    wmma::mma_sync(accO[n], pl, vh, accO[n]);
                }
            }
        }
    }

    // ---- epilogue: stage O, write unnormalized partials + l
    __syncthreads();
    #pragma unroll
    for (int n = 0; n < 4; ++n)
        wmma::store_matrix_sync(Ps + w * 16 * PAD + n * 16, accO[n], PAD,
                                wmma::mem_row_major);
    __syncthreads();

    const float lsum = l_acc + __shfl_xor_sync(0xffffffffu, l_acc, 1);
    if ((tid & 1) == 0)
        g_lpart[split][batch * SEQ + row_g] = lsum;

    float* op = &g_Opart[split][((size_t)batch * SEQ + row_g) * HDIM];
    #pragma unroll
    for (int j = 0; j < 8; ++j) {
        const int c = chalf + j * 4;
        *(float4*)&op[c] = *(const float4*)&Ps[srow * PAD + c];
    }
}

// ---------------------------------------------------------------------------
// Combine split-KV partials: out = (O0 + O1) / (l0 + l1)
// ---------------------------------------------------------------------------
__global__ __launch_bounds__(256) void combine_kernel(float* __restrict__ out)
{
    const int idx = blockIdx.x * 256 + threadIdx.x;
    const int r   = idx >> 6;
    const float lsum = g_lpart[0][r] + g_lpart[1][r];
    out[idx] = (g_Opart[0][idx] + g_Opart[1][idx]) / lsum;
}

extern "C" void kernel_launch(void* const* d_in, const int* in_sizes, int n_in,
                              void* d_out, int out_size)
{
    const float* x  = (const float*)d_in[0];   // [B, L, D] fp32
    const float* Wq = (const float*)d_in[1];   // [H, D] fp32
    float* out = (float*)d_out;                // [B, L, H] fp32

    cudaFuncSetAttribute(attn_mma_kernel,
                         cudaFuncAttributeMaxDynamicSharedMemorySize,
                         ATTN_SMEM_BYTES);

    proj_kernel<<<(BATCH * SEQ) / 32, 256>>>(x, Wq);
    bmax_kernel<<<BATCH, 256>>>();
    attn_mma_kernel<<<dim3(64, BATCH), 128, ATTN_SMEM_BYTES>>>();
    combine_kernel<<<(BATCH * SEQ * HDIM) / 256, 256>>>(out);
}

// round 11
// speedup vs baseline: 1.6752x; 1.6752x over previous
#include <cuda_runtime.h>
#include <cuda_bf16.h>
#include <math_constants.h>
#include <mma.h>
#include <cstdint>

using namespace nvcuda;

#define BATCH  4
#define SEQ    2048
#define DMODEL 1024
#define HDIM   64
#define SCALE  0.03125f   // 1/sqrt(1024)

#define BQ     128        // q-rows per CTA
#define BK     64         // keys per tile
#define SB     72         // bf16 row stride (144B: ldmatrix conflict-free)
#define SF     68         // fp32 row stride for S staging

// ---------------------------------------------------------------------------
// Global scratch (allocation-free rule: __device__ arrays)
// ---------------------------------------------------------------------------
__device__ float g_q[BATCH * SEQ * HDIM];        // projected q (= k = v), fp32
__device__ float g_norm[BATCH * SEQ];            // |q_row|
__device__ float g_bmax[BATCH];                  // max row norm per batch
__device__ float g_Opart[2][BATCH * SEQ * HDIM]; // split-KV partial O
__device__ float g_lpart[2][BATCH * SEQ];        // split-KV partial l

// ---------------------------------------------------------------------------
// Projection: q = x · Wq^T  (proven round-4 core) + row norms.
// ---------------------------------------------------------------------------
__global__ __launch_bounds__(256) void proj_kernel(const float* __restrict__ x,
                                                   const float* __restrict__ wq)
{
    __shared__ float Xs[32][68];
    __shared__ float Wsm[64][68];

    const int m0  = blockIdx.x * 32;
    const int tid = threadIdx.x;
    const int w   = tid >> 5;
    const int l   = tid & 31;

    float c[4][2] = {};

    for (int kt = 0; kt < DMODEL; kt += 64) {
        __syncthreads();
        #pragma unroll
        for (int u = 0; u < 2; ++u) {
            const int f = u * 256 + tid;
            const int r = f >> 4;
            const int cc = (f & 15) << 2;
            *(float4*)&Xs[r][cc] = *(const float4*)(x + (size_t)(m0 + r) * DMODEL + kt + cc);
        }
        #pragma unroll
        for (int u = 0; u < 4; ++u) {
            const int f = u * 256 + tid;
            const int r = f >> 4;
            const int cc = (f & 15) << 2;
            *(float4*)&Wsm[r][cc] = *(const float4*)(wq + (size_t)r * DMODEL + kt + cc);
        }
        __syncthreads();

        #pragma unroll
        for (int k = 0; k < 64; k += 4) {
            float4 a[4], b[2];
            #pragma unroll
            for (int i = 0; i < 4; ++i) a[i] = *(const float4*)&Xs[4 * w + i][k];
            b[0] = *(const float4*)&Wsm[l][k];
            b[1] = *(const float4*)&Wsm[l + 32][k];
            #pragma unroll
            for (int i = 0; i < 4; ++i) {
                #pragma unroll
                for (int m = 0; m < 2; ++m) {
                    c[i][m] = fmaf(a[i].x, b[m].x, c[i][m]);
                    c[i][m] = fmaf(a[i].y, b[m].y, c[i][m]);
                    c[i][m] = fmaf(a[i].z, b[m].z, c[i][m]);
                    c[i][m] = fmaf(a[i].w, b[m].w, c[i][m]);
                }
            }
        }
    }

    #pragma unroll
    for (int i = 0; i < 4; ++i) {
        const int row = m0 + 4 * w + i;
        g_q[(size_t)row * HDIM + l]      = c[i][0];
        g_q[(size_t)row * HDIM + l + 32] = c[i][1];
        float n2 = c[i][0] * c[i][0] + c[i][1] * c[i][1];
        #pragma unroll
        for (int off = 16; off > 0; off >>= 1)
            n2 += __shfl_xor_sync(0xffffffffu, n2, off);
        if (l == 0) g_norm[row] = sqrtf(n2);
    }
}

// ---------------------------------------------------------------------------
// Per-batch max of row norms.
// ---------------------------------------------------------------------------
__global__ __launch_bounds__(256) void bmax_kernel()
{
    __shared__ float red[8];
    const int b   = blockIdx.x;
    const int tid = threadIdx.x;
    float m = 0.0f;
    for (int i = tid; i < SEQ; i += 256)
        m = fmaxf(m, g_norm[b * SEQ + i]);
    #pragma unroll
    for (int off = 16; off > 0; off >>= 1)
        m = fmaxf(m, __shfl_xor_sync(0xffffffffu, m, off));
    if ((tid & 31) == 0) red[tid >> 5] = m;
    __syncthreads();
    if (tid == 0) {
        float r = red[0];
        #pragma unroll
        for (int i = 1; i < 8; ++i) r = fmaxf(r, red[i]);
        g_bmax[b] = r;
    }
}

// ---------------------------------------------------------------------------
// bf16 split helpers
// ---------------------------------------------------------------------------
__device__ __forceinline__ uint32_t pack_raw(__nv_bfloat16 a, __nv_bfloat16 b) {
    return (uint32_t)__bfloat16_as_ushort(a) |
           ((uint32_t)__bfloat16_as_ushort(b) << 16);
}

// split float4 -> (2x u32 hi bf16, 2x u32 lo bf16)
__device__ __forceinline__ void split4(float4 v, uint2& hw, uint2& lw) {
    __nv_bfloat16 h0 = __float2bfloat16(v.x);
    __nv_bfloat16 h1 = __float2bfloat16(v.y);
    __nv_bfloat16 h2 = __float2bfloat16(v.z);
    __nv_bfloat16 h3 = __float2bfloat16(v.w);
    hw.x = pack_raw(h0, h1);
    hw.y = pack_raw(h2, h3);
    lw.x = pack_raw(__float2bfloat16(v.x - __bfloat162float(h0)),
                    __float2bfloat16(v.y - __bfloat162float(h1)));
    lw.y = pack_raw(__float2bfloat16(v.z - __bfloat162float(h2)),
                    __float2bfloat16(v.w - __bfloat162float(h3)));
}

// ---------------------------------------------------------------------------
// Tensor-core (wmma bf16 hi/lo 3-pass) causal attention with q = k = v.
// CTA: 128 q-rows, 64-key tiles, 256 threads (8 warps x 16-row strips).
// Static-max softmax (proven): p = exp(s*scale - Mrow); O accumulates in
// wmma fragments across tiles. Split-KV x2. grid = (32, BATCH).
// ---------------------------------------------------------------------------
#define OFF_QHI 0
#define OFF_QLO (OFF_QHI + BQ * SB * 2)
#define OFF_KHI (OFF_QLO + BQ * SB * 2)
#define OFF_KLO (OFF_KHI + BK * SB * 2)
#define OFF_PHI (OFF_KLO + BK * SB * 2)
#define OFF_PLO (OFF_PHI + BQ * SB * 2)
#define OFF_PS  (OFF_PLO + BQ * SB * 2)
#define ATTN_SMEM_BYTES (OFF_PS + BQ * SF * 4)

__global__ __launch_bounds__(256) void attn_mma_kernel()
{
    extern __shared__ unsigned char smraw[];
    __nv_bfloat16* Qhi = (__nv_bfloat16*)(smraw + OFF_QHI);
    __nv_bfloat16* Qlo = (__nv_bfloat16*)(smraw + OFF_QLO);
    __nv_bfloat16* Khi = (__nv_bfloat16*)(smraw + OFF_KHI);
    __nv_bfloat16* Klo = (__nv_bfloat16*)(smraw + OFF_KLO);
    __nv_bfloat16* Phi = (__nv_bfloat16*)(smraw + OFF_PHI);
    __nv_bfloat16* Plo = (__nv_bfloat16*)(smraw + OFF_PLO);
    float*         Ps  = (float*)(smraw + OFF_PS);

    const int tid   = threadIdx.x;
    const int w     = tid >> 5;
    const int qb    = 15 - ((int)blockIdx.x >> 1);   // heavy row-blocks first
    const int split = blockIdx.x & 1;
    const int batch = blockIdx.y;
    const float* qbase = g_q + (size_t)batch * SEQ * HDIM;

    // ---- prologue: Q tile (BQ x 64) -> bf16 hi/lo
    #pragma unroll
    for (int u = 0; u < 8; ++u) {
        const int idx = u * 256 + tid;            // float4 index 0..2047
        const int r   = idx >> 4;
        const int c4  = (idx & 15) << 2;
        float4 v = *(const float4*)(qbase + (size_t)(qb * BQ + r) * HDIM + c4);
        uint2 hw, lw;
        split4(v, hw, lw);
        *(uint2*)(Qhi + r * SB + c4) = hw;
        *(uint2*)(Qlo + r * SB + c4) = lw;
    }

    const int srow  = tid >> 1;                   // softmax row 0..127
    const int chalf = (tid & 1) * 32;             // column half
    const int row_g = qb * BQ + srow;
    const float Mrow = g_norm[batch * SEQ + row_g] * g_bmax[batch] * SCALE;
    float l_acc = 0.0f;

    wmma::fragment<wmma::accumulator, 16, 16, 16, float> accO[4];
    #pragma unroll
    for (int n = 0; n < 4; ++n) wmma::fill_fragment(accO[n], 0.0f);

    const int nT = 2 * qb + 2;
    const int h  = qb + 1;
    const int k0 = split ? h : 0;
    const int k1 = split ? nT : h;

    for (int kt = k0; kt < k1; ++kt) {
        __syncthreads();   // prev PV done reading Khi/Klo/Phi/Plo; Q ready
        // ---- K (=V) tile -> bf16 hi/lo
        #pragma unroll
        for (int u = 0; u < 4; ++u) {
            const int idx = u * 256 + tid;        // 0..1023
            const int r   = idx >> 4;
            const int c4  = (idx & 15) << 2;
            float4 v = *(const float4*)(qbase + (size_t)(kt * BK + r) * HDIM + c4);
            uint2 hw, lw;
            split4(v, hw, lw);
            *(uint2*)(Khi + r * SB + c4) = hw;
            *(uint2*)(Klo + r * SB + c4) = lw;
        }
        __syncthreads();

        // ---- S = Q · K^T  (bf16 3-pass), warp strip = 16 rows x 64 keys
        {
            wmma::fragment<wmma::accumulator, 16, 16, 16, float> accS[4];
            #pragma unroll
            for (int n = 0; n < 4; ++n) wmma::fill_fragment(accS[n], 0.0f);

            wmma::fragment<wmma::matrix_a, 16, 16, 16, __nv_bfloat16, wmma::row_major> ah, al;
            wmma::fragment<wmma::matrix_b, 16, 16, 16, __nv_bfloat16, wmma::col_major> bh, bl;

            #pragma unroll
            for (int ks = 0; ks < 4; ++ks) {
                wmma::load_matrix_sync(ah, Qhi + (w * 16) * SB + ks * 16, SB);
                wmma::load_matrix_sync(al, Qlo + (w * 16) * SB + ks * 16, SB);
                #pragma unroll
                for (int n = 0; n < 4; ++n) {
                    wmma::load_matrix_sync(bh, Khi + (n * 16) * SB + ks * 16, SB);
                    wmma::load_matrix_sync(bl, Klo + (n * 16) * SB + ks * 16, SB);
                    wmma::mma_sync(accS[n], ah, bh, accS[n]);
                    wmma::mma_sync(accS[n], ah, bl, accS[n]);
                    wmma::mma_sync(accS[n], al, bh, accS[n]);
                }
            }
            #pragma unroll
            for (int n = 0; n < 4; ++n)
                wmma::store_matrix_sync(Ps + (w * 16) * SF + n * 16, accS[n], SF,
                                        wmma::mem_row_major);
        }
        __syncthreads();

        // ---- softmax (static max) + causal mask; P -> bf16 hi/lo
        #pragma unroll
        for (int j = 0; j < 8; ++j) {
            const int c = chalf + j * 4;
            float4 s4 = *(const float4*)&Ps[srow * SF + c];
            float p[4] = {s4.x, s4.y, s4.z, s4.w};
            #pragma unroll
            for (int e = 0; e < 4; ++e) {
                const int col_g = kt * BK + c + e;
                float pe = __expf(fmaf(p[e], SCALE, -Mrow));
                pe = (col_g > row_g) ? 0.0f : pe;
                p[e] = pe;
                l_acc += pe;
            }
            float4 pv = {p[0], p[1], p[2], p[3]};
            uint2 hw, lw;
            split4(pv, hw, lw);
            *(uint2*)(Phi + srow * SB + c) = hw;
            *(uint2*)(Plo + srow * SB + c) = lw;
        }
        __syncthreads();

        // ---- O += P · V  (V == K tile, row-major B), bf16 3-pass
        {
            wmma::fragment<wmma::matrix_a, 16, 16, 16, __nv_bfloat16, wmma::row_major> ph, pl;
            wmma::fragment<wmma::matrix_b, 16, 16, 16, __nv_bfloat16, wmma::row_major> vh, vl;
            #pragma unroll
            for (int ks = 0; ks < 4; ++ks) {
                wmma::load_matrix_sync(ph, Phi + (w * 16) * SB + ks * 16, SB);
                wmma::load_matrix_sync(pl, Plo + (w * 16) * SB + ks * 16, SB);
                #pragma unroll
                for (int n = 0; n < 4; ++n) {
                    wmma::load_matrix_sync(vh, Khi + (ks * 16) * SB + n * 16, SB);
                    wmma::load_matrix_sync(vl, Klo + (ks * 16) * SB + n * 16, SB);
                    wmma::mma_sync(accO[n], ph, vh, accO[n]);
                    wmma::mma_sync(accO[n], ph, vl, accO[n]);
                    wmma::mma_sync(accO[n], pl, vh, accO[n]);
                }
            }
        }
    }

    // ---- epilogue: stage O, write unnormalized partials + l
    __syncthreads();
    #pragma unroll
    for (int n = 0; n < 4; ++n)
        wmma::store_matrix_sync(Ps + (w * 16) * SF + n * 16, accO[n], SF,
                                wmma::mem_row_major);
    __syncthreads();

    const float lsum = l_acc + __shfl_xor_sync(0xffffffffu, l_acc, 1);
    if ((tid & 1) == 0)
        g_lpart[split][batch * SEQ + row_g] = lsum;

    float* op = &g_Opart[split][((size_t)batch * SEQ + row_g) * HDIM];
    #pragma unroll
    for (int j = 0; j < 8; ++j) {
        const int c = chalf + j * 4;
        *(float4*)&op[c] = *(const float4*)&Ps[srow * SF + c];
    }
}

// ---------------------------------------------------------------------------
// Combine split-KV partials: out = (O0 + O1) / (l0 + l1)
// ---------------------------------------------------------------------------
__global__ __launch_bounds__(256) void combine_kernel(float* __restrict__ out)
{
    const int idx = blockIdx.x * 256 + threadIdx.x;
    const int r   = idx >> 6;
    const float lsum = g_lpart[0][r] + g_lpart[1][r];
    out[idx] = (g_Opart[0][idx] + g_Opart[1][idx]) / lsum;
}

extern "C" void kernel_launch(void* const* d_in, const int* in_sizes, int n_in,
                              void* d_out, int out_size)
{
    const float* x  = (const float*)d_in[0];   // [B, L, D] fp32
    const float* Wq = (const float*)d_in[1];   // [H, D] fp32
    float* out = (float*)d_out;                // [B, L, H] fp32

    cudaFuncSetAttribute(attn_mma_kernel,
                         cudaFuncAttributeMaxDynamicSharedMemorySize,
                         ATTN_SMEM_BYTES);

    proj_kernel<<<(BATCH * SEQ) / 32, 256>>>(x, Wq);
    bmax_kernel<<<BATCH, 256>>>();
    attn_mma_kernel<<<dim3(32, BATCH), 256, ATTN_SMEM_BYTES>>>();
    combine_kernel<<<(BATCH * SEQ * HDIM) / 256, 256>>>(out);
}

// round 12
// speedup vs baseline: 1.7292x; 1.0323x over previous
#include <cuda_runtime.h>
#include <cuda_bf16.h>
#include <math_constants.h>
#include <mma.h>
#include <cstdint>

using namespace nvcuda;

#define BATCH  4
#define SEQ    2048
#define DMODEL 1024
#define HDIM   64
#define SCALE  0.03125f   // 1/sqrt(1024)

#define BQ     128        // q-rows per attention CTA
#define BK     64         // keys per tile
#define SB     72         // bf16 row stride (144B: ldmatrix conflict-free)
#define SF     68         // fp32 row stride for S staging

// ---------------------------------------------------------------------------
// Global scratch (allocation-free rule: __device__ arrays)
// ---------------------------------------------------------------------------
__device__ __nv_bfloat16 g_qhi[BATCH * SEQ * HDIM]; // q hi [row][dim]
__device__ __nv_bfloat16 g_qlo[BATCH * SEQ * HDIM]; // q lo
__device__ float g_norm[BATCH * SEQ];               // |q_row|
__device__ float g_bmax[BATCH];                     // max row norm per batch
__device__ float g_Opart[2][BATCH * SEQ * HDIM];    // split-KV partial O
__device__ float g_lpart[2][BATCH * SEQ];           // split-KV partial l

// ---------------------------------------------------------------------------
// bf16 split helpers
// ---------------------------------------------------------------------------
__device__ __forceinline__ uint32_t pack_raw(__nv_bfloat16 a, __nv_bfloat16 b) {
    return (uint32_t)__bfloat16_as_ushort(a) |
           ((uint32_t)__bfloat16_as_ushort(b) << 16);
}

__device__ __forceinline__ void split4(float4 v, uint2& hw, uint2& lw) {
    __nv_bfloat16 h0 = __float2bfloat16(v.x);
    __nv_bfloat16 h1 = __float2bfloat16(v.y);
    __nv_bfloat16 h2 = __float2bfloat16(v.z);
    __nv_bfloat16 h3 = __float2bfloat16(v.w);
    hw.x = pack_raw(h0, h1);
    hw.y = pack_raw(h2, h3);
    lw.x = pack_raw(__float2bfloat16(v.x - __bfloat162float(h0)),
                    __float2bfloat16(v.y - __bfloat162float(h1)));
    lw.y = pack_raw(__float2bfloat16(v.z - __bfloat162float(h2)),
                    __float2bfloat16(v.w - __bfloat162float(h3)));
}

// ---------------------------------------------------------------------------
// Projection (bf16 wmma 3-pass): q = x · Wq^T, emit bf16 hi/lo + row norms.
// M=8192, N=64, K=1024. BM=64/CTA, 128 threads (4 warps x 16 rows), 128 CTAs.
// ---------------------------------------------------------------------------
#define POFF_XHI 0
#define POFF_XLO (POFF_XHI + 64 * SB * 2)
#define POFF_WHI (POFF_XLO + 64 * SB * 2)
#define POFF_WLO (POFF_WHI + 64 * SB * 2)
#define POFF_ST  (POFF_WLO + 64 * SB * 2)
#define PROJ_SMEM_BYTES (POFF_ST + 64 * SF * 4)

__global__ __launch_bounds__(128) void proj_mma_kernel(const float* __restrict__ x,
                                                       const float* __restrict__ wq)
{
    extern __shared__ unsigned char psm[];
    __nv_bfloat16* Xhi = (__nv_bfloat16*)(psm + POFF_XHI);
    __nv_bfloat16* Xlo = (__nv_bfloat16*)(psm + POFF_XLO);
    __nv_bfloat16* Whi = (__nv_bfloat16*)(psm + POFF_WHI);
    __nv_bfloat16* Wlo = (__nv_bfloat16*)(psm + POFF_WLO);
    float*         Stg = (float*)(psm + POFF_ST);

    const int tid = threadIdx.x;
    const int w   = tid >> 5;
    const int m0  = blockIdx.x * 64;

    wmma::fragment<wmma::accumulator, 16, 16, 16, float> accC[4];
    #pragma unroll
    for (int n = 0; n < 4; ++n) wmma::fill_fragment(accC[n], 0.0f);

    for (int kt = 0; kt < DMODEL; kt += 64) {
        __syncthreads();   // previous MMAs done reading tiles
        // load + split x tile (64x64) and W tile (64x64)
        #pragma unroll
        for (int u = 0; u < 8; ++u) {
            const int idx = u * 128 + tid;     // float4 idx 0..1023
            const int r   = idx >> 4;
            const int c4  = (idx & 15) << 2;
            float4 v = *(const float4*)(x + (size_t)(m0 + r) * DMODEL + kt + c4);
            uint2 hw, lw;
            split4(v, hw, lw);
            *(uint2*)(Xhi + r * SB + c4) = hw;
            *(uint2*)(Xlo + r * SB + c4) = lw;
            float4 vw = *(const float4*)(wq + (size_t)r * DMODEL + kt + c4);
            split4(vw, hw, lw);
            *(uint2*)(Whi + r * SB + c4) = hw;
            *(uint2*)(Wlo + r * SB + c4) = lw;
        }
        __syncthreads();

        wmma::fragment<wmma::matrix_a, 16, 16, 16, __nv_bfloat16, wmma::row_major> ah, al;
        wmma::fragment<wmma::matrix_b, 16, 16, 16, __nv_bfloat16, wmma::col_major> bh, bl;
        #pragma unroll
        for (int ks = 0; ks < 4; ++ks) {
            wmma::load_matrix_sync(ah, Xhi + (w * 16) * SB + ks * 16, SB);
            wmma::load_matrix_sync(al, Xlo + (w * 16) * SB + ks * 16, SB);
            #pragma unroll
            for (int n = 0; n < 4; ++n) {
                wmma::load_matrix_sync(bh, Whi + (n * 16) * SB + ks * 16, SB);
                wmma::load_matrix_sync(bl, Wlo + (n * 16) * SB + ks * 16, SB);
                wmma::mma_sync(accC[n], ah, bh, accC[n]);
                wmma::mma_sync(accC[n], ah, bl, accC[n]);
                wmma::mma_sync(accC[n], al, bh, accC[n]);
            }
        }
    }

    __syncthreads();
    #pragma unroll
    for (int n = 0; n < 4; ++n)
        wmma::store_matrix_sync(Stg + (w * 16) * SF + n * 16, accC[n], SF,
                                wmma::mem_row_major);
    __syncthreads();

    // epilogue: split to bf16 hi/lo gmem + row norms
    const int srow  = tid >> 1;              // 0..63
    const int chalf = (tid & 1) * 32;
    const int row   = m0 + srow;
    float n2 = 0.0f;
    #pragma unroll
    for (int j = 0; j < 8; ++j) {
        const int c = chalf + j * 4;
        float4 v = *(const float4*)&Stg[srow * SF + c];
        n2 += v.x * v.x + v.y * v.y + v.z * v.z + v.w * v.w;
        uint2 hw, lw;
        split4(v, hw, lw);
        *(uint2*)(g_qhi + (size_t)row * HDIM + c) = hw;
        *(uint2*)(g_qlo + (size_t)row * HDIM + c) = lw;
    }
    n2 += __shfl_xor_sync(0xffffffffu, n2, 1);
    if ((tid & 1) == 0) g_norm[row] = sqrtf(n2);
}

// ---------------------------------------------------------------------------
// Per-batch max of row norms.
// ---------------------------------------------------------------------------
__global__ __launch_bounds__(256) void bmax_kernel()
{
    __shared__ float red[8];
    const int b   = blockIdx.x;
    const int tid = threadIdx.x;
    float m = 0.0f;
    for (int i = tid; i < SEQ; i += 256)
        m = fmaxf(m, g_norm[b * SEQ + i]);
    #pragma unroll
    for (int off = 16; off > 0; off >>= 1)
        m = fmaxf(m, __shfl_xor_sync(0xffffffffu, m, off));
    if ((tid & 31) == 0) red[tid >> 5] = m;
    __syncthreads();
    if (tid == 0) {
        float r = red[0];
        #pragma unroll
        for (int i = 1; i < 8; ++i) r = fmaxf(r, red[i]);
        g_bmax[b] = r;
    }
}

// ---------------------------------------------------------------------------
// Tensor-core (wmma bf16 hi/lo 3-pass) causal attention with q = k = v.
// CTA: 128 q-rows, 64-key tiles, 256 threads (8 warps x 16-row strips).
// Q/K tiles loaded as pre-split bf16 (raw uint4 copies, no conversion).
// Static-max softmax; O accumulates in fragments; split-KV x2; grid (32, B).
// ---------------------------------------------------------------------------
#define OFF_QHI 0
#define OFF_QLO (OFF_QHI + BQ * SB * 2)
#define OFF_KHI (OFF_QLO + BQ * SB * 2)
#define OFF_KLO (OFF_KHI + BK * SB * 2)
#define OFF_PHI (OFF_KLO + BK * SB * 2)
#define OFF_PLO (OFF_PHI + BQ * SB * 2)
#define OFF_PS  (OFF_PLO + BQ * SB * 2)
#define ATTN_SMEM_BYTES (OFF_PS + BQ * SF * 4)

__global__ __launch_bounds__(256) void attn_mma_kernel()
{
    extern __shared__ unsigned char smraw[];
    __nv_bfloat16* Qhi = (__nv_bfloat16*)(smraw + OFF_QHI);
    __nv_bfloat16* Qlo = (__nv_bfloat16*)(smraw + OFF_QLO);
    __nv_bfloat16* Khi = (__nv_bfloat16*)(smraw + OFF_KHI);
    __nv_bfloat16* Klo = (__nv_bfloat16*)(smraw + OFF_KLO);
    __nv_bfloat16* Phi = (__nv_bfloat16*)(smraw + OFF_PHI);
    __nv_bfloat16* Plo = (__nv_bfloat16*)(smraw + OFF_PLO);
    float*         Ps  = (float*)(smraw + OFF_PS);

    const int tid   = threadIdx.x;
    const int w     = tid >> 5;
    const int qb    = 15 - ((int)blockIdx.x >> 1);   // heavy row-blocks first
    const int split = blockIdx.x & 1;
    const int batch = blockIdx.y;
    const uint4* qh4 = (const uint4*)(g_qhi + (size_t)batch * SEQ * HDIM);
    const uint4* ql4 = (const uint4*)(g_qlo + (size_t)batch * SEQ * HDIM);

    // ---- prologue: Q tile (BQ x 64 bf16 hi/lo) raw copy; row = 8 uint4
    #pragma unroll
    for (int u = 0; u < 4; ++u) {
        const int idx = u * 256 + tid;        // uint4 idx 0..1023
        const int r   = idx >> 3;
        const int c8  = idx & 7;
        *(uint4*)(Qhi + r * SB + c8 * 8) = qh4[(qb * BQ + r) * 8 + c8];
        *(uint4*)(Qlo + r * SB + c8 * 8) = ql4[(qb * BQ + r) * 8 + c8];
    }

    const int srow  = tid >> 1;                   // softmax row 0..127
    const int chalf = (tid & 1) * 32;             // column half
    const int row_g = qb * BQ + srow;
    const float Mrow = g_norm[batch * SEQ + row_g] * g_bmax[batch] * SCALE;
    float l_acc = 0.0f;

    wmma::fragment<wmma::accumulator, 16, 16, 16, float> accO[4];
    #pragma unroll
    for (int n = 0; n < 4; ++n) wmma::fill_fragment(accO[n], 0.0f);

    const int nT = 2 * qb + 2;
    const int h  = qb + 1;
    const int k0 = split ? h : 0;
    const int k1 = split ? nT : h;

    for (int kt = k0; kt < k1; ++kt) {
        __syncthreads();   // prev PV done reading Khi/Klo/Phi/Plo; Q ready
        // ---- K (=V) tile raw copy (64 x 64 bf16 hi/lo)
        #pragma unroll
        for (int u = 0; u < 2; ++u) {
            const int idx = u * 256 + tid;    // uint4 idx 0..511
            const int r   = idx >> 3;
            const int c8  = idx & 7;
            *(uint4*)(Khi + r * SB + c8 * 8) = qh4[(kt * BK + r) * 8 + c8];
            *(uint4*)(Klo + r * SB + c8 * 8) = ql4[(kt * BK + r) * 8 + c8];
        }
        __syncthreads();

        // ---- S = Q · K^T  (bf16 3-pass), warp strip = 16 rows x 64 keys
        {
            wmma::fragment<wmma::accumulator, 16, 16, 16, float> accS[4];
            #pragma unroll
            for (int n = 0; n < 4; ++n) wmma::fill_fragment(accS[n], 0.0f);

            wmma::fragment<wmma::matrix_a, 16, 16, 16, __nv_bfloat16, wmma::row_major> ah, al;
            wmma::fragment<wmma::matrix_b, 16, 16, 16, __nv_bfloat16, wmma::col_major> bh, bl;

            #pragma unroll
            for (int ks = 0; ks < 4; ++ks) {
                wmma::load_matrix_sync(ah, Qhi + (w * 16) * SB + ks * 16, SB);
                wmma::load_matrix_sync(al, Qlo + (w * 16) * SB + ks * 16, SB);
                #pragma unroll
                for (int n = 0; n < 4; ++n) {
                    wmma::load_matrix_sync(bh, Khi + (n * 16) * SB + ks * 16, SB);
                    wmma::load_matrix_sync(bl, Klo + (n * 16) * SB + ks * 16, SB);
                    wmma::mma_sync(accS[n], ah, bh, accS[n]);
                    wmma::mma_sync(accS[n], ah, bl, accS[n]);
                    wmma::mma_sync(accS[n], al, bh, accS[n]);
                }
            }
            #pragma unroll
            for (int n = 0; n < 4; ++n)
                wmma::store_matrix_sync(Ps + (w * 16) * SF + n * 16, accS[n], SF,
                                        wmma::mem_row_major);
        }
        __syncthreads();

        // ---- softmax (static max) + causal mask; P -> bf16 hi/lo
        #pragma unroll
        for (int j = 0; j < 8; ++j) {
            const int c = chalf + j * 4;
            float4 s4 = *(const float4*)&Ps[srow * SF + c];
            float p[4] = {s4.x, s4.y, s4.z, s4.w};
            #pragma unroll
            for (int e = 0; e < 4; ++e) {
                const int col_g = kt * BK + c + e;
                float pe = __expf(fmaf(p[e], SCALE, -Mrow));
                pe = (col_g > row_g) ? 0.0f : pe;
                p[e] = pe;
                l_acc += pe;
            }
            float4 pv = {p[0], p[1], p[2], p[3]};
            uint2 hw, lw;
            split4(pv, hw, lw);
            *(uint2*)(Phi + srow * SB + c) = hw;
            *(uint2*)(Plo + srow * SB + c) = lw;
        }
        __syncthreads();

        // ---- O += P · V  (V == K tile, row-major B), bf16 3-pass
        {
            wmma::fragment<wmma::matrix_a, 16, 16, 16, __nv_bfloat16, wmma::row_major> ph, pl;
            wmma::fragment<wmma::matrix_b, 16, 16, 16, __nv_bfloat16, wmma::row_major> vh, vl;
            #pragma unroll
            for (int ks = 0; ks < 4; ++ks) {
                wmma::load_matrix_sync(ph, Phi + (w * 16) * SB + ks * 16, SB);
                wmma::load_matrix_sync(pl, Plo + (w * 16) * SB + ks * 16, SB);
                #pragma unroll
                for (int n = 0; n < 4; ++n) {
                    wmma::load_matrix_sync(vh, Khi + (ks * 16) * SB + n * 16, SB);
                    wmma::load_matrix_sync(vl, Klo + (ks * 16) * SB + n * 16, SB);
                    wmma::mma_sync(accO[n], ph, vh, accO[n]);
                    wmma::mma_sync(accO[n], ph, vl, accO[n]);
                    wmma::mma_sync(accO[n], pl, vh, accO[n]);
                }
            }
        }
    }

    // ---- epilogue: stage O, write unnormalized partials + l
    __syncthreads();
    #pragma unroll
    for (int n = 0; n < 4; ++n)
        wmma::store_matrix_sync(Ps + (w * 16) * SF + n * 16, accO[n], SF,
                                wmma::mem_row_major);
    __syncthreads();

    const float lsum = l_acc + __shfl_xor_sync(0xffffffffu, l_acc, 1);
    if ((tid & 1) == 0)
        g_lpart[split][batch * SEQ + row_g] = lsum;

    float* op = &g_Opart[split][((size_t)batch * SEQ + row_g) * HDIM];
    #pragma unroll
    for (int j = 0; j < 8; ++j) {
        const int c = chalf + j * 4;
        *(float4*)&op[c] = *(const float4*)&Ps[srow * SF + c];
    }
}

// ---------------------------------------------------------------------------
// Combine split-KV partials: out = (O0 + O1) / (l0 + l1)
// ---------------------------------------------------------------------------
__global__ __launch_bounds__(256) void combine_kernel(float* __restrict__ out)
{
    const int idx = blockIdx.x * 256 + threadIdx.x;
    const int r   = idx >> 6;
    const float lsum = g_lpart[0][r] + g_lpart[1][r];
    out[idx] = (g_Opart[0][idx] + g_Opart[1][idx]) / lsum;
}

extern "C" void kernel_launch(void* const* d_in, const int* in_sizes, int n_in,
                              void* d_out, int out_size)
{
    const float* x  = (const float*)d_in[0];   // [B, L, D] fp32
    const float* Wq = (const float*)d_in[1];   // [H, D] fp32
    float* out = (float*)d_out;                // [B, L, H] fp32

    cudaFuncSetAttribute(proj_mma_kernel,
                         cudaFuncAttributeMaxDynamicSharedMemorySize,
                         PROJ_SMEM_BYTES);
    cudaFuncSetAttribute(attn_mma_kernel,
                         cudaFuncAttributeMaxDynamicSharedMemorySize,
                         ATTN_SMEM_BYTES);

    proj_mma_kernel<<<(BATCH * SEQ) / 64, 128, PROJ_SMEM_BYTES>>>(x, Wq);
    bmax_kernel<<<BATCH, 256>>>();
    attn_mma_kernel<<<dim3(32, BATCH), 256, ATTN_SMEM_BYTES>>>();
    combine_kernel<<<(BATCH * SEQ * HDIM) / 256, 256>>>(out);
}

// round 14
// speedup vs baseline: 2.4595x; 1.4223x over previous
#include <cuda_runtime.h>
#include <cuda_bf16.h>
#include <math_constants.h>
#include <mma.h>
#include <cstdint>

using namespace nvcuda;

#define BATCH  4
#define SEQ    2048
#define DMODEL 1024
#define HDIM   64
#define SCALE  0.03125f   // 1/sqrt(1024)

#define BQ     128        // q-rows per attention CTA
#define BK     64         // keys per tile
#define SB     72         // bf16 row stride (144B: ldmatrix conflict-free)
#define SF     68         // fp32 row stride for staging

// ---------------------------------------------------------------------------
// Global scratch (allocation-free rule: __device__ arrays)
// ---------------------------------------------------------------------------
__device__ __nv_bfloat16 g_qhi[BATCH * SEQ * HDIM]; // q hi [row][dim]
__device__ __nv_bfloat16 g_qlo[BATCH * SEQ * HDIM]; // q lo
__device__ float g_norm[BATCH * SEQ];               // |q_row|
__device__ float g_bmax[BATCH];                     // max row norm per batch
__device__ float g_Opart[2][BATCH * SEQ * HDIM];    // split-KV partial O
__device__ float g_lpart[2][BATCH * SEQ];           // split-KV partial l

// ---------------------------------------------------------------------------
// helpers
// ---------------------------------------------------------------------------
__device__ __forceinline__ uint32_t smem_u32(const void* p) {
    uint32_t a;
    asm("{ .reg .u64 t; cvta.to.shared.u64 t, %1; cvt.u32.u64 %0, t; }"
        : "=r"(a) : "l"(p));
    return a;
}

__device__ __forceinline__ uint32_t pack_raw(__nv_bfloat16 a, __nv_bfloat16 b) {
    return (uint32_t)__bfloat16_as_ushort(a) |
           ((uint32_t)__bfloat16_as_ushort(b) << 16);
}

__device__ __forceinline__ void split4(float4 v, uint2& hw, uint2& lw) {
    __nv_bfloat16 h0 = __float2bfloat16(v.x);
    __nv_bfloat16 h1 = __float2bfloat16(v.y);
    __nv_bfloat16 h2 = __float2bfloat16(v.z);
    __nv_bfloat16 h3 = __float2bfloat16(v.w);
    hw.x = pack_raw(h0, h1);
    hw.y = pack_raw(h2, h3);
    lw.x = pack_raw(__float2bfloat16(v.x - __bfloat162float(h0)),
                    __float2bfloat16(v.y - __bfloat162float(h1)));
    lw.y = pack_raw(__float2bfloat16(v.z - __bfloat162float(h2)),
                    __float2bfloat16(v.w - __bfloat162float(h3)));
}

// pack two floats -> bf16x2 (lo = a, hi = b)
__device__ __forceinline__ uint32_t pack2bf(float a, float b) {
    uint32_t r;
    asm("cvt.rn.bf16x2.f32 %0, %1, %2;" : "=r"(r) : "f"(b), "f"(a));
    return r;
}

__device__ __forceinline__ void ldmx4(uint32_t* r, uint32_t addr) {
    asm volatile("ldmatrix.sync.aligned.m8n8.x4.shared.b16 {%0,%1,%2,%3}, [%4];"
                 : "=r"(r[0]), "=r"(r[1]), "=r"(r[2]), "=r"(r[3]) : "r"(addr));
}
__device__ __forceinline__ void ldmx4t(uint32_t* r, uint32_t addr) {
    asm volatile("ldmatrix.sync.aligned.m8n8.x4.trans.shared.b16 {%0,%1,%2,%3}, [%4];"
                 : "=r"(r[0]), "=r"(r[1]), "=r"(r[2]), "=r"(r[3]) : "r"(addr));
}
__device__ __forceinline__ void mma16816(float* c, const uint32_t* a,
                                         uint32_t b0, uint32_t b1) {
    asm volatile(
        "mma.sync.aligned.m16n8k16.row.col.f32.bf16.bf16.f32 "
        "{%0,%1,%2,%3}, {%4,%5,%6,%7}, {%8,%9}, {%0,%1,%2,%3};"
        : "+f"(c[0]), "+f"(c[1]), "+f"(c[2]), "+f"(c[3])
        : "r"(a[0]), "r"(a[1]), "r"(a[2]), "r"(a[3]), "r"(b0), "r"(b1));
}
__device__ __forceinline__ void cpasync16(uint32_t dst, const void* src) {
    asm volatile("cp.async.cg.shared.global [%0], [%1], 16;"
                 :: "r"(dst), "l"(src));
}
__device__ __forceinline__ void cp_commit() {
    asm volatile("cp.async.commit_group;");
}
__device__ __forceinline__ void cp_wait0() {
    asm volatile("cp.async.wait_group 0;" ::: "memory");
}

// ---------------------------------------------------------------------------
// Projection (bf16 wmma 3-pass): q = x · Wq^T, emit bf16 hi/lo + row norms.
// (Proven R12 kernel, unchanged.)
// ---------------------------------------------------------------------------
#define POFF_XHI 0
#define POFF_XLO (POFF_XHI + 64 * SB * 2)
#define POFF_WHI (POFF_XLO + 64 * SB * 2)
#define POFF_WLO (POFF_WHI + 64 * SB * 2)
#define POFF_ST  (POFF_WLO + 64 * SB * 2)
#define PROJ_SMEM_BYTES (POFF_ST + 64 * SF * 4)

__global__ __launch_bounds__(128) void proj_mma_kernel(const float* __restrict__ x,
                                                       const float* __restrict__ wq)
{
    extern __shared__ unsigned char psm[];
    __nv_bfloat16* Xhi = (__nv_bfloat16*)(psm + POFF_XHI);
    __nv_bfloat16* Xlo = (__nv_bfloat16*)(psm + POFF_XLO);
    __nv_bfloat16* Whi = (__nv_bfloat16*)(psm + POFF_WHI);
    __nv_bfloat16* Wlo = (__nv_bfloat16*)(psm + POFF_WLO);
    float*         Stg = (float*)(psm + POFF_ST);

    const int tid = threadIdx.x;
    const int w   = tid >> 5;
    const int m0  = blockIdx.x * 64;

    wmma::fragment<wmma::accumulator, 16, 16, 16, float> accC[4];
    #pragma unroll
    for (int n = 0; n < 4; ++n) wmma::fill_fragment(accC[n], 0.0f);

    for (int kt = 0; kt < DMODEL; kt += 64) {
        __syncthreads();
        #pragma unroll
        for (int u = 0; u < 8; ++u) {
            const int idx = u * 128 + tid;
            const int r   = idx >> 4;
            const int c4  = (idx & 15) << 2;
            float4 v = *(const float4*)(x + (size_t)(m0 + r) * DMODEL + kt + c4);
            uint2 hw, lw;
            split4(v, hw, lw);
            *(uint2*)(Xhi + r * SB + c4) = hw;
            *(uint2*)(Xlo + r * SB + c4) = lw;
            float4 vw = *(const float4*)(wq + (size_t)r * DMODEL + kt + c4);
            split4(vw, hw, lw);
            *(uint2*)(Whi + r * SB + c4) = hw;
            *(uint2*)(Wlo + r * SB + c4) = lw;
        }
        __syncthreads();

        wmma::fragment<wmma::matrix_a, 16, 16, 16, __nv_bfloat16, wmma::row_major> ah, al;
        wmma::fragment<wmma::matrix_b, 16, 16, 16, __nv_bfloat16, wmma::col_major> bh, bl;
        #pragma unroll
        for (int ks = 0; ks < 4; ++ks) {
            wmma::load_matrix_sync(ah, Xhi + (w * 16) * SB + ks * 16, SB);
            wmma::load_matrix_sync(al, Xlo + (w * 16) * SB + ks * 16, SB);
            #pragma unroll
            for (int n = 0; n < 4; ++n) {
                wmma::load_matrix_sync(bh, Whi + (n * 16) * SB + ks * 16, SB);
                wmma::load_matrix_sync(bl, Wlo + (n * 16) * SB + ks * 16, SB);
                wmma::mma_sync(accC[n], ah, bh, accC[n]);
                wmma::mma_sync(accC[n], ah, bl, accC[n]);
                wmma::mma_sync(accC[n], al, bh, accC[n]);
            }
        }
    }

    __syncthreads();
    #pragma unroll
    for (int n = 0; n < 4; ++n)
        wmma::store_matrix_sync(Stg + (w * 16) * SF + n * 16, accC[n], SF,
                                wmma::mem_row_major);
    __syncthreads();

    const int srow  = tid >> 1;
    const int chalf = (tid & 1) * 32;
    const int row   = m0 + srow;
    float n2 = 0.0f;
    #pragma unroll
    for (int j = 0; j < 8; ++j) {
        const int c = chalf + j * 4;
        float4 v = *(const float4*)&Stg[srow * SF + c];
        n2 += v.x * v.x + v.y * v.y + v.z * v.z + v.w * v.w;
        uint2 hw, lw;
        split4(v, hw, lw);
        *(uint2*)(g_qhi + (size_t)row * HDIM + c) = hw;
        *(uint2*)(g_qlo + (size_t)row * HDIM + c) = lw;
    }
    n2 += __shfl_xor_sync(0xffffffffu, n2, 1);
    if ((tid & 1) == 0) g_norm[row] = sqrtf(n2);
}

// ---------------------------------------------------------------------------
// Per-batch max of row norms.
// ---------------------------------------------------------------------------
__global__ __launch_bounds__(256) void bmax_kernel()
{
    __shared__ float red[8];
    const int b   = blockIdx.x;
    const int tid = threadIdx.x;
    float m = 0.0f;
    for (int i = tid; i < SEQ; i += 256)
        m = fmaxf(m, g_norm[b * SEQ + i]);
    #pragma unroll
    for (int off = 16; off > 0; off >>= 1)
        m = fmaxf(m, __shfl_xor_sync(0xffffffffu, m, off));
    if ((tid & 31) == 0) red[tid >> 5] = m;
    __syncthreads();
    if (tid == 0) {
        float r = red[0];
        #pragma unroll
        for (int i = 1; i < 8; ++i) r = fmaxf(r, red[i]);
        g_bmax[b] = r;
    }
}

// ---------------------------------------------------------------------------
// FA2-style register-resident causal attention (mma.m16n8k16 bf16, 3-pass).
// CTA: 128 q-rows, 64-key tiles, 256 threads (8 warps x 16-row strips).
// S in accumulators -> softmax in registers -> P repacked reg-to-reg into
// A-fragments for PV. K tile double-buffered via cp.async. 1 sync per tile.
// Static-max softmax; O accumulates in registers; split-KV x2; grid (32, B).
// ---------------------------------------------------------------------------
#define QREG_BYTES (BQ * SB * 2)          // 18432 (one Q plane)
#define OFF_QLO    QREG_BYTES
#define OFF_K      (2 * QREG_BYTES)       // 36864
#define KREG       (BK * SB * 2)          // 9216 (one K plane)
#define KBUF       (2 * KREG)             // 18432 (hi+lo per buffer)
#define ATTN_SMEM_BYTES (OFF_K + 2 * KBUF)  // 73728

__global__ __launch_bounds__(256) void attn_mma_kernel()
{
    extern __shared__ unsigned char smraw[];
    __nv_bfloat16* Qhi = (__nv_bfloat16*)(smraw);
    __nv_bfloat16* Qlo = (__nv_bfloat16*)(smraw + OFF_QLO);
    float*         Ostg = (float*)(smraw);        // epilogue reuse of Q region

    const uint32_t smb = smem_u32(smraw);

    const int tid   = threadIdx.x;
    const int w     = tid >> 5;
    const int t     = tid & 31;
    const int qb    = 15 - ((int)blockIdx.x >> 1);   // heavy row-blocks first
    const int split = blockIdx.x & 1;
    const int batch = blockIdx.y;
    const uint4* qh4 = (const uint4*)(g_qhi + (size_t)batch * SEQ * HDIM);
    const uint4* ql4 = (const uint4*)(g_qlo + (size_t)batch * SEQ * HDIM);

    const int nT = 2 * qb + 2;
    const int h  = qb + 1;
    const int k0 = split ? h : 0;
    const int k1 = split ? nT : h;

    // ---- prologue: Q tile into SMEM (raw bf16 copies)
    #pragma unroll
    for (int u = 0; u < 4; ++u) {
        const int idx = u * 256 + tid;        // uint4 idx 0..1023
        const int r   = idx >> 3;
        const int c8  = idx & 7;
        *(uint4*)(Qhi + r * SB + c8 * 8) = qh4[(qb * BQ + r) * 8 + c8];
        *(uint4*)(Qlo + r * SB + c8 * 8) = ql4[(qb * BQ + r) * 8 + c8];
    }
    // ---- prefetch first K tile into buffer 0
    {
        const uint32_t kb = smb + OFF_K;
        #pragma unroll
        for (int u = 0; u < 2; ++u) {
            const int idx = u * 256 + tid;    // uint4 idx 0..511
            const int r   = idx >> 3;
            const int c8  = idx & 7;
            cpasync16(kb + (r * SB + c8 * 8) * 2, &qh4[(k0 * BK + r) * 8 + c8]);
            cpasync16(kb + KREG + (r * SB + c8 * 8) * 2, &ql4[(k0 * BK + r) * 8 + c8]);
        }
        cp_commit();
    }
    __syncthreads();

    // ---- hoist Q fragments (loop-invariant): 4 k-steps x (hi, lo)
    uint32_t qfh[4][4], qfl[4][4];
    {
        const int qrow  = w * 16 + (t & 15);
        const int qcol0 = (t >> 4) * 8;
        #pragma unroll
        for (int ks = 0; ks < 4; ++ks) {
            const uint32_t a = smb + (qrow * SB + ks * 16 + qcol0) * 2;
            ldmx4(qfh[ks], a);
            ldmx4(qfl[ks], a + OFF_QLO);
        }
    }

    const int r0 = qb * BQ + w * 16 + (t >> 2);   // rows r0, r0+8
    const float bm = g_bmax[batch];
    const float M0 = g_norm[batch * SEQ + r0]     * bm * SCALE;
    const float M1 = g_norm[batch * SEQ + r0 + 8] * bm * SCALE;

    float oc[8][4];
    #pragma unroll
    for (int j = 0; j < 8; ++j)
        #pragma unroll
        for (int e = 0; e < 4; ++e) oc[j][e] = 0.0f;
    float l0 = 0.0f, l1 = 0.0f;

    // per-thread ldmatrix address components
    const int skey = ((t >> 4) & 1) * 8 + (t & 7);  // S (non-trans B)
    const int scol = ((t >> 3) & 1) * 8;
    const int vkey = ((t >> 3) & 1) * 8 + (t & 7);  // PV (trans B)
    const int vdim = ((t >> 4) & 1) * 8;

    for (int kt = k0; kt < k1; ++kt) {
        cp_wait0();
        __syncthreads();   // K tile kt visible to all; prev tile fully consumed

        // prefetch next tile into the other buffer
        if (kt + 1 < k1) {
            const uint32_t kb = smb + OFF_K + ((kt + 1 - k0) & 1) * KBUF;
            #pragma unroll
            for (int u = 0; u < 2; ++u) {
                const int idx = u * 256 + tid;
                const int r   = idx >> 3;
                const int c8  = idx & 7;
                cpasync16(kb + (r * SB + c8 * 8) * 2,
                          &qh4[((kt + 1) * BK + r) * 8 + c8]);
                cpasync16(kb + KREG + (r * SB + c8 * 8) * 2,
                          &ql4[((kt + 1) * BK + r) * 8 + c8]);
            }
        }
        cp_commit();

        const uint32_t kb = smb + OFF_K + ((kt - k0) & 1) * KBUF;

        // ---- S = Q · K^T (bf16 3-pass), accumulators in registers
        float sc[8][4];
        #pragma unroll
        for (int j = 0; j < 8; ++j)
            #pragma unroll
            for (int e = 0; e < 4; ++e) sc[j][e] = 0.0f;

        #pragma unroll
        for (int ks = 0; ks < 4; ++ks) {
            #pragma unroll
            for (int jp = 0; jp < 4; ++jp) {
                const uint32_t off = ((16 * jp + skey) * SB + ks * 16 + scol) * 2;
                uint32_t bh[4], bl[4];
                ldmx4(bh, kb + off);
                ldmx4(bl, kb + KREG + off);
                mma16816(sc[2 * jp],     qfh[ks], bh[0], bh[1]);
                mma16816(sc[2 * jp],     qfh[ks], bl[0], bl[1]);
                mma16816(sc[2 * jp],     qfl[ks], bh[0], bh[1]);
                mma16816(sc[2 * jp + 1], qfh[ks], bh[2], bh[3]);
                mma16816(sc[2 * jp + 1], qfh[ks], bl[2], bl[3]);
                mma16816(sc[2 * jp + 1], qfl[ks], bh[2], bh[3]);
            }
        }

        // ---- softmax in registers (static max) + causal mask; pack P hi/lo
        const bool needMask = (kt >= 2 * qb);
        uint32_t phi[4][4], plo[4][4];
        #pragma unroll
        for (int j = 0; j < 8; ++j) {
            float p0 = __expf(fmaf(sc[j][0], SCALE, -M0));
            float p1 = __expf(fmaf(sc[j][1], SCALE, -M0));
            float p2 = __expf(fmaf(sc[j][2], SCALE, -M1));
            float p3 = __expf(fmaf(sc[j][3], SCALE, -M1));
            if (needMask) {
                const int c0 = kt * BK + j * 8 + (t & 3) * 2;
                p0 = (c0     > r0    ) ? 0.0f : p0;
                p1 = (c0 + 1 > r0    ) ? 0.0f : p1;
                p2 = (c0     > r0 + 8) ? 0.0f : p2;
                p3 = (c0 + 1 > r0 + 8) ? 0.0f : p3;
            }
            l0 += p0 + p1;
            l1 += p2 + p3;
            const int kv = j >> 1;
            const uint32_t h01 = pack2bf(p0, p1);
            const uint32_t h23 = pack2bf(p2, p3);
            const uint32_t l01 = pack2bf(p0 - __uint_as_float(h01 << 16),
                                         p1 - __uint_as_float(h01 & 0xffff0000u));
            const uint32_t l23 = pack2bf(p2 - __uint_as_float(h23 << 16),
                                         p3 - __uint_as_float(h23 & 0xffff0000u));
            if ((j & 1) == 0) {
                phi[kv][0] = h01; phi[kv][1] = h23;
                plo[kv][0] = l01; plo[kv][1] = l23;
            } else {
                phi[kv][2] = h01; phi[kv][3] = h23;
                plo[kv][2] = l01; plo[kv][3] = l23;
            }
        }

        // ---- O += P · V (V == K tile via ldmatrix.trans), bf16 3-pass
        #pragma unroll
        for (int kv = 0; kv < 4; ++kv) {
            #pragma unroll
            for (int jp = 0; jp < 4; ++jp) {
                const uint32_t off = ((kv * 16 + vkey) * SB + 16 * jp + vdim) * 2;
                uint32_t vh[4], vl[4];
                ldmx4t(vh, kb + off);
                ldmx4t(vl, kb + KREG + off);
                mma16816(oc[2 * jp],     phi[kv], vh[0], vh[1]);
                mma16816(oc[2 * jp],     phi[kv], vl[0], vl[1]);
                mma16816(oc[2 * jp],     plo[kv], vh[0], vh[1]);
                mma16816(oc[2 * jp + 1], phi[kv], vh[2], vh[3]);
                mma16816(oc[2 * jp + 1], phi[kv], vl[2], vl[3]);
                mma16816(oc[2 * jp + 1], plo[kv], vh[2], vh[3]);
            }
        }
    }

    // ---- epilogue: l reduction + stage O to SMEM (Q region reuse)
    l0 += __shfl_xor_sync(0xffffffffu, l0, 1);
    l0 += __shfl_xor_sync(0xffffffffu, l0, 2);
    l1 += __shfl_xor_sync(0xffffffffu, l1, 1);
    l1 += __shfl_xor_sync(0xffffffffu, l1, 2);
    if ((t & 3) == 0) {
        g_lpart[split][batch * SEQ + r0]     = l0;
        g_lpart[split][batch * SEQ + r0 + 8] = l1;
    }

    __syncthreads();   // all warps done with K smem / loop before Q-region reuse
    {
        const int rl = w * 16 + (t >> 2);
        #pragma unroll
        for (int j = 0; j < 8; ++j) {
            const int c = j * 8 + (t & 3) * 2;
            Ostg[rl * SF + c]           = oc[j][0];
            Ostg[rl * SF + c + 1]       = oc[j][1];
            Ostg[(rl + 8) * SF + c]     = oc[j][2];
            Ostg[(rl + 8) * SF + c + 1] = oc[j][3];
        }
    }
    __syncthreads();

    // coalesced write of unnormalized partial O
    const int srow  = tid >> 1;
    const int chalf = (tid & 1) * 32;
    float* op = &g_Opart[split][((size_t)batch * SEQ + qb * BQ + srow) * HDIM];
    #pragma unroll
    for (int j = 0; j < 8; ++j) {
        const int c = chalf + j * 4;
        *(float4*)&op[c] = *(const float4*)&Ostg[srow * SF + c];
    }
}

// ---------------------------------------------------------------------------
// Combine split-KV partials: out = (O0 + O1) / (l0 + l1)
// ---------------------------------------------------------------------------
__global__ __launch_bounds__(256) void combine_kernel(float* __restrict__ out)
{
    const int idx = blockIdx.x * 256 + threadIdx.x;
    const int r   = idx >> 6;
    const float lsum = g_lpart[0][r] + g_lpart[1][r];
    out[idx] = (g_Opart[0][idx] + g_Opart[1][idx]) / lsum;
}

extern "C" void kernel_launch(void* const* d_in, const int* in_sizes, int n_in,
                              void* d_out, int out_size)
{
    const float* x  = (const float*)d_in[0];   // [B, L, D] fp32
    const float* Wq = (const float*)d_in[1];   // [H, D] fp32
    float* out = (float*)d_out;                // [B, L, H] fp32

    cudaFuncSetAttribute(proj_mma_kernel,
                         cudaFuncAttributeMaxDynamicSharedMemorySize,
                         PROJ_SMEM_BYTES);
    cudaFuncSetAttribute(attn_mma_kernel,
                         cudaFuncAttributeMaxDynamicSharedMemorySize,
                         ATTN_SMEM_BYTES);

    proj_mma_kernel<<<(BATCH * SEQ) / 64, 128, PROJ_SMEM_BYTES>>>(x, Wq);
    bmax_kernel<<<BATCH, 256>>>();
    attn_mma_kernel<<<dim3(32, BATCH), 256, ATTN_SMEM_BYTES>>>();
    combine_kernel<<<(BATCH * SEQ * HDIM) / 256, 256>>>(out);
}

// round 15
// speedup vs baseline: 2.7822x; 1.1312x over previous
#include <cuda_runtime.h>
#include <cuda_bf16.h>
#include <math_constants.h>
#include <mma.h>
#include <cstdint>

#define BATCH  4
#define SEQ    2048
#define DMODEL 1024
#define HDIM   64
#define SCALE  0.03125f   // 1/sqrt(1024)

#define BQ     128        // q-rows per attention CTA
#define BK     64         // keys per tile
#define SB     72         // bf16 row stride (144B: ldmatrix conflict-free)
#define SF     68         // fp32 row stride for staging

// ---------------------------------------------------------------------------
// Global scratch (allocation-free rule: __device__ arrays)
// ---------------------------------------------------------------------------
__device__ __nv_bfloat16 g_qhi[BATCH * SEQ * HDIM]; // q hi [row][dim]
__device__ __nv_bfloat16 g_qlo[BATCH * SEQ * HDIM]; // q lo
__device__ float g_norm[BATCH * SEQ];               // |q_row|
__device__ float g_bmax[BATCH];                     // max row norm per batch
__device__ float g_Opart[2][BATCH * SEQ * HDIM];    // split-KV partial O
__device__ float g_lpart[2][BATCH * SEQ];           // split-KV partial l

// ---------------------------------------------------------------------------
// helpers
// ---------------------------------------------------------------------------
__device__ __forceinline__ uint32_t smem_u32(const void* p) {
    uint32_t a;
    asm("{ .reg .u64 t; cvta.to.shared.u64 t, %1; cvt.u32.u64 %0, t; }"
        : "=r"(a) : "l"(p));
    return a;
}

__device__ __forceinline__ uint32_t pack_raw(__nv_bfloat16 a, __nv_bfloat16 b) {
    return (uint32_t)__bfloat16_as_ushort(a) |
           ((uint32_t)__bfloat16_as_ushort(b) << 16);
}

__device__ __forceinline__ void split4(float4 v, uint2& hw, uint2& lw) {
    __nv_bfloat16 h0 = __float2bfloat16(v.x);
    __nv_bfloat16 h1 = __float2bfloat16(v.y);
    __nv_bfloat16 h2 = __float2bfloat16(v.z);
    __nv_bfloat16 h3 = __float2bfloat16(v.w);
    hw.x = pack_raw(h0, h1);
    hw.y = pack_raw(h2, h3);
    lw.x = pack_raw(__float2bfloat16(v.x - __bfloat162float(h0)),
                    __float2bfloat16(v.y - __bfloat162float(h1)));
    lw.y = pack_raw(__float2bfloat16(v.z - __bfloat162float(h2)),
                    __float2bfloat16(v.w - __bfloat162float(h3)));
}

// pack two floats -> bf16x2 (lo = a, hi = b)
__device__ __forceinline__ uint32_t pack2bf(float a, float b) {
    uint32_t r;
    asm("cvt.rn.bf16x2.f32 %0, %1, %2;" : "=r"(r) : "f"(b), "f"(a));
    return r;
}

__device__ __forceinline__ void ldmx4(uint32_t* r, uint32_t addr) {
    asm volatile("ldmatrix.sync.aligned.m8n8.x4.shared.b16 {%0,%1,%2,%3}, [%4];"
                 : "=r"(r[0]), "=r"(r[1]), "=r"(r[2]), "=r"(r[3]) : "r"(addr));
}
__device__ __forceinline__ void ldmx4t(uint32_t* r, uint32_t addr) {
    asm volatile("ldmatrix.sync.aligned.m8n8.x4.trans.shared.b16 {%0,%1,%2,%3}, [%4];"
                 : "=r"(r[0]), "=r"(r[1]), "=r"(r[2]), "=r"(r[3]) : "r"(addr));
}
__device__ __forceinline__ void mma16816(float* c, const uint32_t* a,
                                         uint32_t b0, uint32_t b1) {
    asm volatile(
        "mma.sync.aligned.m16n8k16.row.col.f32.bf16.bf16.f32 "
        "{%0,%1,%2,%3}, {%4,%5,%6,%7}, {%8,%9}, {%0,%1,%2,%3};"
        : "+f"(c[0]), "+f"(c[1]), "+f"(c[2]), "+f"(c[3])
        : "r"(a[0]), "r"(a[1]), "r"(a[2]), "r"(a[3]), "r"(b0), "r"(b1));
}
__device__ __forceinline__ void cpasync16(uint32_t dst, const void* src) {
    asm volatile("cp.async.cg.shared.global [%0], [%1], 16;"
                 :: "r"(dst), "l"(src));
}
__device__ __forceinline__ void cp_commit() {
    asm volatile("cp.async.commit_group;");
}
__device__ __forceinline__ void cp_wait0() {
    asm volatile("cp.async.wait_group 0;" ::: "memory");
}

// ---------------------------------------------------------------------------
// Projection v2 (FA2-style): q = x · Wq^T via raw mma bf16 3-pass,
// register accumulators over all of K=1024, cp.async double-buffered staging.
// BM=64, 256 threads (8 warps: rows (w&3)*16, col half (w>>2)*32), 128 CTAs.
// ---------------------------------------------------------------------------
#define PSTG   (64 * SF * 4)              // 17408: one fp32 staging buffer
#define PXF    0                          // XF0, XF1
#define PWF    (2 * PSTG)                 // WF0, WF1
#define PXHI   (4 * PSTG)                 // bf16 planes: 64*SB*2 = 9216 each
#define PPLANE (64 * SB * 2)
#define PXLO   (PXHI + PPLANE)
#define PWHI   (PXLO + PPLANE)
#define PWLO   (PWHI + PPLANE)
#define PROJ_SMEM_BYTES (PWLO + PPLANE)   // 106496

__global__ __launch_bounds__(256) void proj_mma_kernel(const float* __restrict__ x,
                                                       const float* __restrict__ wq)
{
    extern __shared__ unsigned char psm[];
    const uint32_t smb = smem_u32(psm);

    const int tid = threadIdx.x;
    const int w   = tid >> 5;
    const int t   = tid & 31;
    const int m0  = blockIdx.x * 64;

    // ---- prefetch tile 0 (fp32 X and W) into buffer 0
    #pragma unroll
    for (int u = 0; u < 4; ++u) {
        const int idx = u * 256 + tid;     // float4 idx 0..1023
        const int r   = idx >> 4;
        const int c4  = (idx & 15) << 2;
        cpasync16(smb + PXF + (r * SF + c4) * 4,
                  x + (size_t)(m0 + r) * DMODEL + c4);
        cpasync16(smb + PWF + (r * SF + c4) * 4,
                  wq + (size_t)r * DMODEL + c4);
    }
    cp_commit();

    float acc[4][4];
    #pragma unroll
    for (int j = 0; j < 4; ++j)
        #pragma unroll
        for (int e = 0; e < 4; ++e) acc[j][e] = 0.0f;

    // fragment address components (proven attn S-GEMM mapping)
    const int arow  = (w & 3) * 16 + (t & 15);
    const int acol0 = (t >> 4) * 8;
    const int skey  = ((t >> 4) & 1) * 8 + (t & 7);
    const int scol  = ((t >> 3) & 1) * 8;
    const int nbase = (w >> 2) * 32;

    for (int kt = 0; kt < DMODEL; kt += 64) {
        cp_wait0();
        __syncthreads();   // staging visible; bf16 planes free (prev reads done)
        const int buf = (kt >> 6) & 1;

        // prefetch next tile into the other staging buffer
        if (kt + 64 < DMODEL) {
            const uint32_t xf = smb + PXF + (buf ^ 1) * PSTG;
            const uint32_t wf = smb + PWF + (buf ^ 1) * PSTG;
            #pragma unroll
            for (int u = 0; u < 4; ++u) {
                const int idx = u * 256 + tid;
                const int r   = idx >> 4;
                const int c4  = (idx & 15) << 2;
                cpasync16(xf + (r * SF + c4) * 4,
                          x + (size_t)(m0 + r) * DMODEL + kt + 64 + c4);
                cpasync16(wf + (r * SF + c4) * 4,
                          wq + (size_t)r * DMODEL + kt + 64 + c4);
            }
        }
        cp_commit();

        // split fp32 staging -> bf16 hi/lo planes
        {
            const float* Xf = (const float*)(psm + PXF + buf * PSTG);
            const float* Wf = (const float*)(psm + PWF + buf * PSTG);
            __nv_bfloat16* Xhi = (__nv_bfloat16*)(psm + PXHI);
            __nv_bfloat16* Xlo = (__nv_bfloat16*)(psm + PXLO);
            __nv_bfloat16* Whi = (__nv_bfloat16*)(psm + PWHI);
            __nv_bfloat16* Wlo = (__nv_bfloat16*)(psm + PWLO);
            #pragma unroll
            for (int u = 0; u < 4; ++u) {
                const int idx = u * 256 + tid;
                const int r   = idx >> 4;
                const int c4  = (idx & 15) << 2;
                uint2 hw, lw;
                float4 v = *(const float4*)&Xf[r * SF + c4];
                split4(v, hw, lw);
                *(uint2*)(Xhi + r * SB + c4) = hw;
                *(uint2*)(Xlo + r * SB + c4) = lw;
                float4 vw = *(const float4*)&Wf[r * SF + c4];
                split4(vw, hw, lw);
                *(uint2*)(Whi + r * SB + c4) = hw;
                *(uint2*)(Wlo + r * SB + c4) = lw;
            }
        }
        __syncthreads();

        // mma (bf16 3-pass), warp = 16 rows x 32 cols
        #pragma unroll
        for (int ks = 0; ks < 4; ++ks) {
            uint32_t afh[4], afl[4];
            const uint32_t a = smb + PXHI + (arow * SB + ks * 16 + acol0) * 2;
            ldmx4(afh, a);
            ldmx4(afl, a + PPLANE);
            #pragma unroll
            for (int jp = 0; jp < 2; ++jp) {
                const uint32_t boff = smb + PWHI +
                    ((nbase + 16 * jp + skey) * SB + ks * 16 + scol) * 2;
                uint32_t bh[4], bl[4];
                ldmx4(bh, boff);
                ldmx4(bl, boff + PPLANE);
                mma16816(acc[2 * jp],     afh, bh[0], bh[1]);
                mma16816(acc[2 * jp],     afh, bl[0], bl[1]);
                mma16816(acc[2 * jp],     afl, bh[0], bh[1]);
                mma16816(acc[2 * jp + 1], afh, bh[2], bh[3]);
                mma16816(acc[2 * jp + 1], afh, bl[2], bl[3]);
                mma16816(acc[2 * jp + 1], afl, bh[2], bh[3]);
            }
        }
    }

    // ---- epilogue: stage accumulators (fp32, reuse staging region)
    __syncthreads();
    float* Stg = (float*)psm;
    {
        const int r0 = (w & 3) * 16 + (t >> 2);
        #pragma unroll
        for (int j2 = 0; j2 < 4; ++j2) {
            const int c = nbase + j2 * 8 + (t & 3) * 2;
            Stg[r0 * SF + c]           = acc[j2][0];
            Stg[r0 * SF + c + 1]       = acc[j2][1];
            Stg[(r0 + 8) * SF + c]     = acc[j2][2];
            Stg[(r0 + 8) * SF + c + 1] = acc[j2][3];
        }
    }
    __syncthreads();

    // split to bf16 hi/lo gmem + row norms (thread -> row tid>>2, 16-col quarter)
    const int row = m0 + (tid >> 2);
    const int cq  = (tid & 3) * 16;
    float n2 = 0.0f;
    #pragma unroll
    for (int j = 0; j < 4; ++j) {
        float4 v = *(const float4*)&Stg[(tid >> 2) * SF + cq + j * 4];
        n2 += v.x * v.x + v.y * v.y + v.z * v.z + v.w * v.w;
        uint2 hw, lw;
        split4(v, hw, lw);
        *(uint2*)(g_qhi + (size_t)row * HDIM + cq + j * 4) = hw;
        *(uint2*)(g_qlo + (size_t)row * HDIM + cq + j * 4) = lw;
    }
    n2 += __shfl_xor_sync(0xffffffffu, n2, 1);
    n2 += __shfl_xor_sync(0xffffffffu, n2, 2);
    if ((tid & 3) == 0) g_norm[row] = sqrtf(n2);
}

// ---------------------------------------------------------------------------
// Per-batch max of row norms.
// ---------------------------------------------------------------------------
__global__ __launch_bounds__(256) void bmax_kernel()
{
    __shared__ float red[8];
    const int b   = blockIdx.x;
    const int tid = threadIdx.x;
    float m = 0.0f;
    for (int i = tid; i < SEQ; i += 256)
        m = fmaxf(m, g_norm[b * SEQ + i]);
    #pragma unroll
    for (int off = 16; off > 0; off >>= 1)
        m = fmaxf(m, __shfl_xor_sync(0xffffffffu, m, off));
    if ((tid & 31) == 0) red[tid >> 5] = m;
    __syncthreads();
    if (tid == 0) {
        float r = red[0];
        #pragma unroll
        for (int i = 1; i < 8; ++i) r = fmaxf(r, red[i]);
        g_bmax[b] = r;
    }
}

// ---------------------------------------------------------------------------
// FA2-style register-resident causal attention (proven R14 kernel, unchanged).
// ---------------------------------------------------------------------------
#define QREG_BYTES (BQ * SB * 2)          // 18432 (one Q plane)
#define OFF_QLO    QREG_BYTES
#define OFF_K      (2 * QREG_BYTES)       // 36864
#define KREG       (BK * SB * 2)          // 9216 (one K plane)
#define KBUF       (2 * KREG)             // 18432 (hi+lo per buffer)
#define ATTN_SMEM_BYTES (OFF_K + 2 * KBUF)  // 73728

__global__ __launch_bounds__(256) void attn_mma_kernel()
{
    extern __shared__ unsigned char smraw[];
    __nv_bfloat16* Qhi = (__nv_bfloat16*)(smraw);
    __nv_bfloat16* Qlo = (__nv_bfloat16*)(smraw + OFF_QLO);
    float*         Ostg = (float*)(smraw);        // epilogue reuse of Q region

    const uint32_t smb = smem_u32(smraw);

    const int tid   = threadIdx.x;
    const int w     = tid >> 5;
    const int t     = tid & 31;
    const int qb    = 15 - ((int)blockIdx.x >> 1);   // heavy row-blocks first
    const int split = blockIdx.x & 1;
    const int batch = blockIdx.y;
    const uint4* qh4 = (const uint4*)(g_qhi + (size_t)batch * SEQ * HDIM);
    const uint4* ql4 = (const uint4*)(g_qlo + (size_t)batch * SEQ * HDIM);

    const int nT = 2 * qb + 2;
    const int h  = qb + 1;
    const int k0 = split ? h : 0;
    const int k1 = split ? nT : h;

    // ---- prologue: Q tile into SMEM (raw bf16 copies)
    #pragma unroll
    for (int u = 0; u < 4; ++u) {
        const int idx = u * 256 + tid;        // uint4 idx 0..1023
        const int r   = idx >> 3;
        const int c8  = idx & 7;
        *(uint4*)(Qhi + r * SB + c8 * 8) = qh4[(qb * BQ + r) * 8 + c8];
        *(uint4*)(Qlo + r * SB + c8 * 8) = ql4[(qb * BQ + r) * 8 + c8];
    }
    // ---- prefetch first K tile into buffer 0
    {
        const uint32_t kb = smb + OFF_K;
        #pragma unroll
        for (int u = 0; u < 2; ++u) {
            const int idx = u * 256 + tid;    // uint4 idx 0..511
            const int r   = idx >> 3;
            const int c8  = idx & 7;
            cpasync16(kb + (r * SB + c8 * 8) * 2, &qh4[(k0 * BK + r) * 8 + c8]);
            cpasync16(kb + KREG + (r * SB + c8 * 8) * 2, &ql4[(k0 * BK + r) * 8 + c8]);
        }
        cp_commit();
    }
    __syncthreads();

    // ---- hoist Q fragments (loop-invariant): 4 k-steps x (hi, lo)
    uint32_t qfh[4][4], qfl[4][4];
    {
        const int qrow  = w * 16 + (t & 15);
        const int qcol0 = (t >> 4) * 8;
        #pragma unroll
        for (int ks = 0; ks < 4; ++ks) {
            const uint32_t a = smb + (qrow * SB + ks * 16 + qcol0) * 2;
            ldmx4(qfh[ks], a);
            ldmx4(qfl[ks], a + OFF_QLO);
        }
    }

    const int r0 = qb * BQ + w * 16 + (t >> 2);   // rows r0, r0+8
    const float bm = g_bmax[batch];
    const float M0 = g_norm[batch * SEQ + r0]     * bm * SCALE;
    const float M1 = g_norm[batch * SEQ + r0 + 8] * bm * SCALE;

    float oc[8][4];
    #pragma unroll
    for (int j = 0; j < 8; ++j)
        #pragma unroll
        for (int e = 0; e < 4; ++e) oc[j][e] = 0.0f;
    float l0 = 0.0f, l1 = 0.0f;

    // per-thread ldmatrix address components
    const int skey = ((t >> 4) & 1) * 8 + (t & 7);  // S (non-trans B)
    const int scol = ((t >> 3) & 1) * 8;
    const int vkey = ((t >> 3) & 1) * 8 + (t & 7);  // PV (trans B)
    const int vdim = ((t >> 4) & 1) * 8;

    for (int kt = k0; kt < k1; ++kt) {
        cp_wait0();
        __syncthreads();   // K tile kt visible to all; prev tile fully consumed

        // prefetch next tile into the other buffer
        if (kt + 1 < k1) {
            const uint32_t kb = smb + OFF_K + ((kt + 1 - k0) & 1) * KBUF;
            #pragma unroll
            for (int u = 0; u < 2; ++u) {
                const int idx = u * 256 + tid;
                const int r   = idx >> 3;
                const int c8  = idx & 7;
                cpasync16(kb + (r * SB + c8 * 8) * 2,
                          &qh4[((kt + 1) * BK + r) * 8 + c8]);
                cpasync16(kb + KREG + (r * SB + c8 * 8) * 2,
                          &ql4[((kt + 1) * BK + r) * 8 + c8]);
            }
        }
        cp_commit();

        const uint32_t kb = smb + OFF_K + ((kt - k0) & 1) * KBUF;

        // ---- S = Q · K^T (bf16 3-pass), accumulators in registers
        float sc[8][4];
        #pragma unroll
        for (int j = 0; j < 8; ++j)
            #pragma unroll
            for (int e = 0; e < 4; ++e) sc[j][e] = 0.0f;

        #pragma unroll
        for (int ks = 0; ks < 4; ++ks) {
            #pragma unroll
            for (int jp = 0; jp < 4; ++jp) {
                const uint32_t off = ((16 * jp + skey) * SB + ks * 16 + scol) * 2;
                uint32_t bh[4], bl[4];
                ldmx4(bh, kb + off);
                ldmx4(bl, kb + KREG + off);
                mma16816(sc[2 * jp],     qfh[ks], bh[0], bh[1]);
                mma16816(sc[2 * jp],     qfh[ks], bl[0], bl[1]);
                mma16816(sc[2 * jp],     qfl[ks], bh[0], bh[1]);
                mma16816(sc[2 * jp + 1], qfh[ks], bh[2], bh[3]);
                mma16816(sc[2 * jp + 1], qfh[ks], bl[2], bl[3]);
                mma16816(sc[2 * jp + 1], qfl[ks], bh[2], bh[3]);
            }
        }

        // ---- softmax in registers (static max) + causal mask; pack P hi/lo
        const bool needMask = (kt >= 2 * qb);
        uint32_t phi[4][4], plo[4][4];
        #pragma unroll
        for (int j = 0; j < 8; ++j) {
            float p0 = __expf(fmaf(sc[j][0], SCALE, -M0));
            float p1 = __expf(fmaf(sc[j][1], SCALE, -M0));
            float p2 = __expf(fmaf(sc[j][2], SCALE, -M1));
            float p3 = __expf(fmaf(sc[j][3], SCALE, -M1));
            if (needMask) {
                const int c0 = kt * BK + j * 8 + (t & 3) * 2;
                p0 = (c0     > r0    ) ? 0.0f : p0;
                p1 = (c0 + 1 > r0    ) ? 0.0f : p1;
                p2 = (c0     > r0 + 8) ? 0.0f : p2;
                p3 = (c0 + 1 > r0 + 8) ? 0.0f : p3;
            }
            l0 += p0 + p1;
            l1 += p2 + p3;
            const int kv = j >> 1;
            const uint32_t h01 = pack2bf(p0, p1);
            const uint32_t h23 = pack2bf(p2, p3);
            const uint32_t l01 = pack2bf(p0 - __uint_as_float(h01 << 16),
                                         p1 - __uint_as_float(h01 & 0xffff0000u));
            const uint32_t l23 = pack2bf(p2 - __uint_as_float(h23 << 16),
                                         p3 - __uint_as_float(h23 & 0xffff0000u));
            if ((j & 1) == 0) {
                phi[kv][0] = h01; phi[kv][1] = h23;
                plo[kv][0] = l01; plo[kv][1] = l23;
            } else {
                phi[kv][2] = h01; phi[kv][3] = h23;
                plo[kv][2] = l01; plo[kv][3] = l23;
            }
        }

        // ---- O += P · V (V == K tile via ldmatrix.trans), bf16 3-pass
        #pragma unroll
        for (int kv = 0; kv < 4; ++kv) {
            #pragma unroll
            for (int jp = 0; jp < 4; ++jp) {
                const uint32_t off = ((kv * 16 + vkey) * SB + 16 * jp + vdim) * 2;
                uint32_t vh[4], vl[4];
                ldmx4t(vh, kb + off);
                ldmx4t(vl, kb + KREG + off);
                mma16816(oc[2 * jp],     phi[kv], vh[0], vh[1]);
                mma16816(oc[2 * jp],     phi[kv], vl[0], vl[1]);
                mma16816(oc[2 * jp],     plo[kv], vh[0], vh[1]);
                mma16816(oc[2 * jp + 1], phi[kv], vh[2], vh[3]);
                mma16816(oc[2 * jp + 1], phi[kv], vl[2], vl[3]);
                mma16816(oc[2 * jp + 1], plo[kv], vh[2], vh[3]);
            }
        }
    }

    // ---- epilogue: l reduction + stage O to SMEM (Q region reuse)
    l0 += __shfl_xor_sync(0xffffffffu, l0, 1);
    l0 += __shfl_xor_sync(0xffffffffu, l0, 2);
    l1 += __shfl_xor_sync(0xffffffffu, l1, 1);
    l1 += __shfl_xor_sync(0xffffffffu, l1, 2);
    if ((t & 3) == 0) {
        g_lpart[split][batch * SEQ + r0]     = l0;
        g_lpart[split][batch * SEQ + r0 + 8] = l1;
    }

    __syncthreads();   // all warps done with K smem / loop before Q-region reuse
    {
        const int rl = w * 16 + (t >> 2);
        #pragma unroll
        for (int j = 0; j < 8; ++j) {
            const int c = j * 8 + (t & 3) * 2;
            Ostg[rl * SF + c]           = oc[j][0];
            Ostg[rl * SF + c + 1]       = oc[j][1];
            Ostg[(rl + 8) * SF + c]     = oc[j][2];
            Ostg[(rl + 8) * SF + c + 1] = oc[j][3];
        }
    }
    __syncthreads();

    // coalesced write of unnormalized partial O
    const int srow  = tid >> 1;
    const int chalf = (tid & 1) * 32;
    float* op = &g_Opart[split][((size_t)batch * SEQ + qb * BQ + srow) * HDIM];
    #pragma unroll
    for (int j = 0; j < 8; ++j) {
        const int c = chalf + j * 4;
        *(float4*)&op[c] = *(const float4*)&Ostg[srow * SF + c];
    }
}

// ---------------------------------------------------------------------------
// Combine split-KV partials: out = (O0 + O1) / (l0 + l1)
// ---------------------------------------------------------------------------
__global__ __launch_bounds__(256) void combine_kernel(float* __restrict__ out)
{
    const int idx = blockIdx.x * 256 + threadIdx.x;
    const int r   = idx >> 6;
    const float lsum = g_lpart[0][r] + g_lpart[1][r];
    out[idx] = (g_Opart[0][idx] + g_Opart[1][idx]) / lsum;
}

extern "C" void kernel_launch(void* const* d_in, const int* in_sizes, int n_in,
                              void* d_out, int out_size)
{
    const float* x  = (const float*)d_in[0];   // [B, L, D] fp32
    const float* Wq = (const float*)d_in[1];   // [H, D] fp32
    float* out = (float*)d_out;                // [B, L, H] fp32

    cudaFuncSetAttribute(proj_mma_kernel,
                         cudaFuncAttributeMaxDynamicSharedMemorySize,
                         PROJ_SMEM_BYTES);
    cudaFuncSetAttribute(attn_mma_kernel,
                         cudaFuncAttributeMaxDynamicSharedMemorySize,
                         ATTN_SMEM_BYTES);

    proj_mma_kernel<<<(BATCH * SEQ) / 64, 256, PROJ_SMEM_BYTES>>>(x, Wq);
    bmax_kernel<<<BATCH, 256>>>();
    attn_mma_kernel<<<dim3(32, BATCH), 256, ATTN_SMEM_BYTES>>>();
    combine_kernel<<<(BATCH * SEQ * HDIM) / 256, 256>>>(out);
}

// round 16
// speedup vs baseline: 3.2189x; 1.1570x over previous
#include <cuda_runtime.h>
#include <cuda_bf16.h>
#include <math_constants.h>
#include <mma.h>
#include <cstdint>

#define BATCH  4
#define SEQ    2048
#define DMODEL 1024
#define HDIM   64
#define SCALE  0.03125f   // 1/sqrt(1024)

#define BQ     128        // q-rows per attention CTA
#define BK     64         // keys per tile
#define SB     72         // bf16 row stride (144B: ldmatrix conflict-free)
#define SF     68         // fp32 row stride for staging
#define NSPLIT 4          // split-KV factor

// ---------------------------------------------------------------------------
// Global scratch (allocation-free rule: __device__ arrays)
// ---------------------------------------------------------------------------
__device__ __nv_bfloat16 g_qhi[BATCH * SEQ * HDIM]; // q hi [row][dim]
__device__ __nv_bfloat16 g_qlo[BATCH * SEQ * HDIM]; // q lo
__device__ float g_norm[BATCH * SEQ];               // |q_row|
__device__ int   g_bmax_i[BATCH];                   // max row norm (int-ordered)
__device__ float g_Opart[NSPLIT][BATCH * SEQ * HDIM]; // split-KV partial O
__device__ float g_lpart[NSPLIT][BATCH * SEQ];        // split-KV partial l

// ---------------------------------------------------------------------------
// helpers
// ---------------------------------------------------------------------------
__device__ __forceinline__ uint32_t smem_u32(const void* p) {
    uint32_t a;
    asm("{ .reg .u64 t; cvta.to.shared.u64 t, %1; cvt.u32.u64 %0, t; }"
        : "=r"(a) : "l"(p));
    return a;
}

__device__ __forceinline__ uint32_t pack_raw(__nv_bfloat16 a, __nv_bfloat16 b) {
    return (uint32_t)__bfloat16_as_ushort(a) |
           ((uint32_t)__bfloat16_as_ushort(b) << 16);
}

__device__ __forceinline__ void split4(float4 v, uint2& hw, uint2& lw) {
    __nv_bfloat16 h0 = __float2bfloat16(v.x);
    __nv_bfloat16 h1 = __float2bfloat16(v.y);
    __nv_bfloat16 h2 = __float2bfloat16(v.z);
    __nv_bfloat16 h3 = __float2bfloat16(v.w);
    hw.x = pack_raw(h0, h1);
    hw.y = pack_raw(h2, h3);
    lw.x = pack_raw(__float2bfloat16(v.x - __bfloat162float(h0)),
                    __float2bfloat16(v.y - __bfloat162float(h1)));
    lw.y = pack_raw(__float2bfloat16(v.z - __bfloat162float(h2)),
                    __float2bfloat16(v.w - __bfloat162float(h3)));
}

// pack two floats -> bf16x2 (lo = a, hi = b)
__device__ __forceinline__ uint32_t pack2bf(float a, float b) {
    uint32_t r;
    asm("cvt.rn.bf16x2.f32 %0, %1, %2;" : "=r"(r) : "f"(b), "f"(a));
    return r;
}

__device__ __forceinline__ void ldmx4(uint32_t* r, uint32_t addr) {
    asm volatile("ldmatrix.sync.aligned.m8n8.x4.shared.b16 {%0,%1,%2,%3}, [%4];"
                 : "=r"(r[0]), "=r"(r[1]), "=r"(r[2]), "=r"(r[3]) : "r"(addr));
}
__device__ __forceinline__ void ldmx4t(uint32_t* r, uint32_t addr) {
    asm volatile("ldmatrix.sync.aligned.m8n8.x4.trans.shared.b16 {%0,%1,%2,%3}, [%4];"
                 : "=r"(r[0]), "=r"(r[1]), "=r"(r[2]), "=r"(r[3]) : "r"(addr));
}
__device__ __forceinline__ void mma16816(float* c, const uint32_t* a,
                                         uint32_t b0, uint32_t b1) {
    asm volatile(
        "mma.sync.aligned.m16n8k16.row.col.f32.bf16.bf16.f32 "
        "{%0,%1,%2,%3}, {%4,%5,%6,%7}, {%8,%9}, {%0,%1,%2,%3};"
        : "+f"(c[0]), "+f"(c[1]), "+f"(c[2]), "+f"(c[3])
        : "r"(a[0]), "r"(a[1]), "r"(a[2]), "r"(a[3]), "r"(b0), "r"(b1));
}
__device__ __forceinline__ void cpasync16(uint32_t dst, const void* src) {
    asm volatile("cp.async.cg.shared.global [%0], [%1], 16;"
                 :: "r"(dst), "l"(src));
}
__device__ __forceinline__ void cp_commit() {
    asm volatile("cp.async.commit_group;");
}
__device__ __forceinline__ void cp_wait0() {
    asm volatile("cp.async.wait_group 0;" ::: "memory");
}

// ---------------------------------------------------------------------------
// Projection (FA2-style, proven R15): q = x · Wq^T via raw mma bf16 3-pass,
// register accumulators over K=1024, cp.async double-buffered staging.
// Epilogue now also folds the per-batch norm max (atomicMax on int bits).
// ---------------------------------------------------------------------------
#define PSTG   (64 * SF * 4)
#define PXF    0
#define PWF    (2 * PSTG)
#define PXHI   (4 * PSTG)
#define PPLANE (64 * SB * 2)
#define PXLO   (PXHI + PPLANE)
#define PWHI   (PXLO + PPLANE)
#define PWLO   (PWHI + PPLANE)
#define PROJ_SMEM_BYTES (PWLO + PPLANE)

__global__ __launch_bounds__(256) void proj_mma_kernel(const float* __restrict__ x,
                                                       const float* __restrict__ wq)
{
    extern __shared__ unsigned char psm[];
    const uint32_t smb = smem_u32(psm);

    const int tid = threadIdx.x;
    const int w   = tid >> 5;
    const int t   = tid & 31;
    const int m0  = blockIdx.x * 64;

    // ---- prefetch tile 0 (fp32 X and W) into buffer 0
    #pragma unroll
    for (int u = 0; u < 4; ++u) {
        const int idx = u * 256 + tid;
        const int r   = idx >> 4;
        const int c4  = (idx & 15) << 2;
        cpasync16(smb + PXF + (r * SF + c4) * 4,
                  x + (size_t)(m0 + r) * DMODEL + c4);
        cpasync16(smb + PWF + (r * SF + c4) * 4,
                  wq + (size_t)r * DMODEL + c4);
    }
    cp_commit();

    float acc[4][4];
    #pragma unroll
    for (int j = 0; j < 4; ++j)
        #pragma unroll
        for (int e = 0; e < 4; ++e) acc[j][e] = 0.0f;

    const int arow  = (w & 3) * 16 + (t & 15);
    const int acol0 = (t >> 4) * 8;
    const int skey  = ((t >> 4) & 1) * 8 + (t & 7);
    const int scol  = ((t >> 3) & 1) * 8;
    const int nbase = (w >> 2) * 32;

    for (int kt = 0; kt < DMODEL; kt += 64) {
        cp_wait0();
        __syncthreads();
        const int buf = (kt >> 6) & 1;

        if (kt + 64 < DMODEL) {
            const uint32_t xf = smb + PXF + (buf ^ 1) * PSTG;
            const uint32_t wf = smb + PWF + (buf ^ 1) * PSTG;
            #pragma unroll
            for (int u = 0; u < 4; ++u) {
                const int idx = u * 256 + tid;
                const int r   = idx >> 4;
                const int c4  = (idx & 15) << 2;
                cpasync16(xf + (r * SF + c4) * 4,
                          x + (size_t)(m0 + r) * DMODEL + kt + 64 + c4);
                cpasync16(wf + (r * SF + c4) * 4,
                          wq + (size_t)r * DMODEL + kt + 64 + c4);
            }
        }
        cp_commit();

        {
            const float* Xf = (const float*)(psm + PXF + buf * PSTG);
            const float* Wf = (const float*)(psm + PWF + buf * PSTG);
            __nv_bfloat16* Xhi = (__nv_bfloat16*)(psm + PXHI);
            __nv_bfloat16* Xlo = (__nv_bfloat16*)(psm + PXLO);
            __nv_bfloat16* Whi = (__nv_bfloat16*)(psm + PWHI);
            __nv_bfloat16* Wlo = (__nv_bfloat16*)(psm + PWLO);
            #pragma unroll
            for (int u = 0; u < 4; ++u) {
                const int idx = u * 256 + tid;
                const int r   = idx >> 4;
                const int c4  = (idx & 15) << 2;
                uint2 hw, lw;
                float4 v = *(const float4*)&Xf[r * SF + c4];
                split4(v, hw, lw);
                *(uint2*)(Xhi + r * SB + c4) = hw;
                *(uint2*)(Xlo + r * SB + c4) = lw;
                float4 vw = *(const float4*)&Wf[r * SF + c4];
                split4(vw, hw, lw);
                *(uint2*)(Whi + r * SB + c4) = hw;
                *(uint2*)(Wlo + r * SB + c4) = lw;
            }
        }
        __syncthreads();

        #pragma unroll
        for (int ks = 0; ks < 4; ++ks) {
            uint32_t afh[4], afl[4];
            const uint32_t a = smb + PXHI + (arow * SB + ks * 16 + acol0) * 2;
            ldmx4(afh, a);
            ldmx4(afl, a + PPLANE);
            #pragma unroll
            for (int jp = 0; jp < 2; ++jp) {
                const uint32_t boff = smb + PWHI +
                    ((nbase + 16 * jp + skey) * SB + ks * 16 + scol) * 2;
                uint32_t bh[4], bl[4];
                ldmx4(bh, boff);
                ldmx4(bl, boff + PPLANE);
                mma16816(acc[2 * jp],     afh, bh[0], bh[1]);
                mma16816(acc[2 * jp],     afh, bl[0], bl[1]);
                mma16816(acc[2 * jp],     afl, bh[0], bh[1]);
                mma16816(acc[2 * jp + 1], afh, bh[2], bh[3]);
                mma16816(acc[2 * jp + 1], afh, bl[2], bl[3]);
                mma16816(acc[2 * jp + 1], afl, bh[2], bh[3]);
            }
        }
    }

    // ---- epilogue: stage accumulators (fp32, reuse staging region)
    __syncthreads();
    float* Stg = (float*)psm;
    {
        const int r0 = (w & 3) * 16 + (t >> 2);
        #pragma unroll
        for (int j2 = 0; j2 < 4; ++j2) {
            const int c = nbase + j2 * 8 + (t & 3) * 2;
            Stg[r0 * SF + c]           = acc[j2][0];
            Stg[r0 * SF + c + 1]       = acc[j2][1];
            Stg[(r0 + 8) * SF + c]     = acc[j2][2];
            Stg[(r0 + 8) * SF + c + 1] = acc[j2][3];
        }
    }
    __syncthreads();

    // split to bf16 hi/lo gmem + row norms + folded batch max
    const int row = m0 + (tid >> 2);
    const int cq  = (tid & 3) * 16;
    float n2 = 0.0f;
    #pragma unroll
    for (int j = 0; j < 4; ++j) {
        float4 v = *(const float4*)&Stg[(tid >> 2) * SF + cq + j * 4];
        n2 += v.x * v.x + v.y * v.y + v.z * v.z + v.w * v.w;
        uint2 hw, lw;
        split4(v, hw, lw);
        *(uint2*)(g_qhi + (size_t)row * HDIM + cq + j * 4) = hw;
        *(uint2*)(g_qlo + (size_t)row * HDIM + cq + j * 4) = lw;
    }
    n2 += __shfl_xor_sync(0xffffffffu, n2, 1);
    n2 += __shfl_xor_sync(0xffffffffu, n2, 2);
    const float nrm = sqrtf(n2);
    if ((tid & 3) == 0) g_norm[row] = nrm;

    // warp max -> one atomicMax per warp (positive floats: int order == fp order)
    float wm = nrm;
    #pragma unroll
    for (int off = 16; off > 0; off >>= 1)
        wm = fmaxf(wm, __shfl_xor_sync(0xffffffffu, wm, off));
    if (t == 0) atomicMax(&g_bmax_i[m0 >> 11], __float_as_int(wm));
}

// ---------------------------------------------------------------------------
// FA2-style register-resident causal attention (proven R14/R15 datapath).
// Now split-KV x4: grid (64, BATCH); qb = 15 - (bx>>2), split = bx&3.
// Chunk = tiles [split*nT/4, (split+1)*nT/4) of nT = 2*qb+2. Empty chunks
// write zero partials. Heavy chunks (8 tiles) launch first (LPT backfill).
// ---------------------------------------------------------------------------
#define QREG_BYTES (BQ * SB * 2)
#define OFF_QLO    QREG_BYTES
#define OFF_K      (2 * QREG_BYTES)
#define KREG       (BK * SB * 2)
#define KBUF       (2 * KREG)
#define ATTN_SMEM_BYTES (OFF_K + 2 * KBUF)

__global__ __launch_bounds__(256) void attn_mma_kernel()
{
    extern __shared__ unsigned char smraw[];
    __nv_bfloat16* Qhi = (__nv_bfloat16*)(smraw);
    __nv_bfloat16* Qlo = (__nv_bfloat16*)(smraw + OFF_QLO);
    float*         Ostg = (float*)(smraw);        // epilogue reuse of Q region

    const uint32_t smb = smem_u32(smraw);

    const int tid   = threadIdx.x;
    const int w     = tid >> 5;
    const int t     = tid & 31;
    const int qb    = 15 - ((int)blockIdx.x >> 2);   // heavy row-blocks first
    const int split = blockIdx.x & 3;
    const int batch = blockIdx.y;
    const uint4* qh4 = (const uint4*)(g_qhi + (size_t)batch * SEQ * HDIM);
    const uint4* ql4 = (const uint4*)(g_qlo + (size_t)batch * SEQ * HDIM);

    const int nT = 2 * qb + 2;
    const int k0 = (split * nT) >> 2;
    const int k1 = ((split + 1) * nT) >> 2;

    // ---- prologue: Q tile into SMEM (raw bf16 copies)
    #pragma unroll
    for (int u = 0; u < 4; ++u) {
        const int idx = u * 256 + tid;        // uint4 idx 0..1023
        const int r   = idx >> 3;
        const int c8  = idx & 7;
        *(uint4*)(Qhi + r * SB + c8 * 8) = qh4[(qb * BQ + r) * 8 + c8];
        *(uint4*)(Qlo + r * SB + c8 * 8) = ql4[(qb * BQ + r) * 8 + c8];
    }
    // ---- prefetch first K tile into buffer 0 (only if non-empty chunk)
    if (k0 < k1) {
        const uint32_t kb = smb + OFF_K;
        #pragma unroll
        for (int u = 0; u < 2; ++u) {
            const int idx = u * 256 + tid;    // uint4 idx 0..511
            const int r   = idx >> 3;
            const int c8  = idx & 7;
            cpasync16(kb + (r * SB + c8 * 8) * 2, &qh4[(k0 * BK + r) * 8 + c8]);
            cpasync16(kb + KREG + (r * SB + c8 * 8) * 2, &ql4[(k0 * BK + r) * 8 + c8]);
        }
        cp_commit();
    }
    __syncthreads();

    // ---- hoist Q fragments (loop-invariant): 4 k-steps x (hi, lo)
    uint32_t qfh[4][4], qfl[4][4];
    {
        const int qrow  = w * 16 + (t & 15);
        const int qcol0 = (t >> 4) * 8;
        #pragma unroll
        for (int ks = 0; ks < 4; ++ks) {
            const uint32_t a = smb + (qrow * SB + ks * 16 + qcol0) * 2;
            ldmx4(qfh[ks], a);
            ldmx4(qfl[ks], a + OFF_QLO);
        }
    }

    const int r0 = qb * BQ + w * 16 + (t >> 2);   // rows r0, r0+8
    const float bm = __int_as_float(g_bmax_i[batch]);
    const float M0 = g_norm[batch * SEQ + r0]     * bm * SCALE;
    const float M1 = g_norm[batch * SEQ + r0 + 8] * bm * SCALE;

    float oc[8][4];
    #pragma unroll
    for (int j = 0; j < 8; ++j)
        #pragma unroll
        for (int e = 0; e < 4; ++e) oc[j][e] = 0.0f;
    float l0 = 0.0f, l1 = 0.0f;

    const int skey = ((t >> 4) & 1) * 8 + (t & 7);  // S (non-trans B)
    const int scol = ((t >> 3) & 1) * 8;
    const int vkey = ((t >> 3) & 1) * 8 + (t & 7);  // PV (trans B)
    const int vdim = ((t >> 4) & 1) * 8;

    for (int kt = k0; kt < k1; ++kt) {
        cp_wait0();
        __syncthreads();   // K tile kt visible to all; prev tile fully consumed

        if (kt + 1 < k1) {
            const uint32_t kb = smb + OFF_K + ((kt + 1 - k0) & 1) * KBUF;
            #pragma unroll
            for (int u = 0; u < 2; ++u) {
                const int idx = u * 256 + tid;
                const int r   = idx >> 3;
                const int c8  = idx & 7;
                cpasync16(kb + (r * SB + c8 * 8) * 2,
                          &qh4[((kt + 1) * BK + r) * 8 + c8]);
                cpasync16(kb + KREG + (r * SB + c8 * 8) * 2,
                          &ql4[((kt + 1) * BK + r) * 8 + c8]);
            }
        }
        cp_commit();

        const uint32_t kb = smb + OFF_K + ((kt - k0) & 1) * KBUF;

        // ---- S = Q · K^T (bf16 3-pass), accumulators in registers
        float sc[8][4];
        #pragma unroll
        for (int j = 0; j < 8; ++j)
            #pragma unroll
            for (int e = 0; e < 4; ++e) sc[j][e] = 0.0f;

        #pragma unroll
        for (int ks = 0; ks < 4; ++ks) {
            #pragma unroll
            for (int jp = 0; jp < 4; ++jp) {
                const uint32_t off = ((16 * jp + skey) * SB + ks * 16 + scol) * 2;
                uint32_t bh[4], bl[4];
                ldmx4(bh, kb + off);
                ldmx4(bl, kb + KREG + off);
                mma16816(sc[2 * jp],     qfh[ks], bh[0], bh[1]);
                mma16816(sc[2 * jp],     qfh[ks], bl[0], bl[1]);
                mma16816(sc[2 * jp],     qfl[ks], bh[0], bh[1]);
                mma16816(sc[2 * jp + 1], qfh[ks], bh[2], bh[3]);
                mma16816(sc[2 * jp + 1], qfh[ks], bl[2], bl[3]);
                mma16816(sc[2 * jp + 1], qfl[ks], bh[2], bh[3]);
            }
        }

        // ---- softmax in registers (static max) + causal mask; pack P hi/lo
        const bool needMask = (kt >= 2 * qb);
        uint32_t phi[4][4], plo[4][4];
        #pragma unroll
        for (int j = 0; j < 8; ++j) {
            float p0 = __expf(fmaf(sc[j][0], SCALE, -M0));
            float p1 = __expf(fmaf(sc[j][1], SCALE, -M0));
            float p2 = __expf(fmaf(sc[j][2], SCALE, -M1));
            float p3 = __expf(fmaf(sc[j][3], SCALE, -M1));
            if (needMask) {
                const int c0 = kt * BK + j * 8 + (t & 3) * 2;
                p0 = (c0     > r0    ) ? 0.0f : p0;
                p1 = (c0 + 1 > r0    ) ? 0.0f : p1;
                p2 = (c0     > r0 + 8) ? 0.0f : p2;
                p3 = (c0 + 1 > r0 + 8) ? 0.0f : p3;
            }
            l0 += p0 + p1;
            l1 += p2 + p3;
            const int kv = j >> 1;
            const uint32_t h01 = pack2bf(p0, p1);
            const uint32_t h23 = pack2bf(p2, p3);
            const uint32_t l01 = pack2bf(p0 - __uint_as_float(h01 << 16),
                                         p1 - __uint_as_float(h01 & 0xffff0000u));
            const uint32_t l23 = pack2bf(p2 - __uint_as_float(h23 << 16),
                                         p3 - __uint_as_float(h23 & 0xffff0000u));
            if ((j & 1) == 0) {
                phi[kv][0] = h01; phi[kv][1] = h23;
                plo[kv][0] = l01; plo[kv][1] = l23;
            } else {
                phi[kv][2] = h01; phi[kv][3] = h23;
                plo[kv][2] = l01; plo[kv][3] = l23;
            }
        }

        // ---- O += P · V (V == K tile via ldmatrix.trans), bf16 3-pass
        #pragma unroll
        for (int kv = 0; kv < 4; ++kv) {
            #pragma unroll
            for (int jp = 0; jp < 4; ++jp) {
                const uint32_t off = ((kv * 16 + vkey) * SB + 16 * jp + vdim) * 2;
                uint32_t vh[4], vl[4];
                ldmx4t(vh, kb + off);
                ldmx4t(vl, kb + KREG + off);
                mma16816(oc[2 * jp],     phi[kv], vh[0], vh[1]);
                mma16816(oc[2 * jp],     phi[kv], vl[0], vl[1]);
                mma16816(oc[2 * jp],     plo[kv], vh[0], vh[1]);
                mma16816(oc[2 * jp + 1], phi[kv], vh[2], vh[3]);
                mma16816(oc[2 * jp + 1], phi[kv], vl[2], vl[3]);
                mma16816(oc[2 * jp + 1], plo[kv], vh[2], vh[3]);
            }
        }
    }

    // ---- epilogue: l reduction + stage O to SMEM (Q region reuse)
    l0 += __shfl_xor_sync(0xffffffffu, l0, 1);
    l0 += __shfl_xor_sync(0xffffffffu, l0, 2);
    l1 += __shfl_xor_sync(0xffffffffu, l1, 1);
    l1 += __shfl_xor_sync(0xffffffffu, l1, 2);
    if ((t & 3) == 0) {
        g_lpart[split][batch * SEQ + r0]     = l0;
        g_lpart[split][batch * SEQ + r0 + 8] = l1;
    }

    __syncthreads();   // all warps done with loop before Q-region reuse
    {
        const int rl = w * 16 + (t >> 2);
        #pragma unroll
        for (int j = 0; j < 8; ++j) {
            const int c = j * 8 + (t & 3) * 2;
            Ostg[rl * SF + c]           = oc[j][0];
            Ostg[rl * SF + c + 1]       = oc[j][1];
            Ostg[(rl + 8) * SF + c]     = oc[j][2];
            Ostg[(rl + 8) * SF + c + 1] = oc[j][3];
        }
    }
    __syncthreads();

    // coalesced write of unnormalized partial O
    const int srow  = tid >> 1;
    const int chalf = (tid & 1) * 32;
    float* op = &g_Opart[split][((size_t)batch * SEQ + qb * BQ + srow) * HDIM];
    #pragma unroll
    for (int j = 0; j < 8; ++j) {
        const int c = chalf + j * 4;
        *(float4*)&op[c] = *(const float4*)&Ostg[srow * SF + c];
    }
}

// ---------------------------------------------------------------------------
// Combine split-KV partials: out = sum(O_s) / sum(l_s)
// ---------------------------------------------------------------------------
__global__ __launch_bounds__(256) void combine_kernel(float* __restrict__ out)
{
    const int idx = blockIdx.x * 256 + threadIdx.x;
    const int r   = idx >> 6;
    const float lsum = g_lpart[0][r] + g_lpart[1][r] +
                       g_lpart[2][r] + g_lpart[3][r];
    const float osum = g_Opart[0][idx] + g_Opart[1][idx] +
                       g_Opart[2][idx] + g_Opart[3][idx];
    out[idx] = osum / lsum;
}

extern "C" void kernel_launch(void* const* d_in, const int* in_sizes, int n_in,
                              void* d_out, int out_size)
{
    const float* x  = (const float*)d_in[0];   // [B, L, D] fp32
    const float* Wq = (const float*)d_in[1];   // [H, D] fp32
    float* out = (float*)d_out;                // [B, L, H] fp32

    cudaFuncSetAttribute(proj_mma_kernel,
                         cudaFuncAttributeMaxDynamicSharedMemorySize,
                         PROJ_SMEM_BYTES);
    cudaFuncSetAttribute(attn_mma_kernel,
                         cudaFuncAttributeMaxDynamicSharedMemorySize,
                         ATTN_SMEM_BYTES);

    proj_mma_kernel<<<(BATCH * SEQ) / 64, 256, PROJ_SMEM_BYTES>>>(x, Wq);
    attn_mma_kernel<<<dim3(16 * NSPLIT, BATCH), 256, ATTN_SMEM_BYTES>>>();
    combine_kernel<<<(BATCH * SEQ * HDIM) / 256, 256>>>(out);
}

// round 17
// speedup vs baseline: 3.6213x; 1.1250x over previous
#include <cuda_runtime.h>
#include <cuda_bf16.h>
#include <math_constants.h>
#include <mma.h>
#include <cstdint>

#define BATCH  4
#define SEQ    2048
#define DMODEL 1024
#define HDIM   64
#define SCALE  0.03125f   // 1/sqrt(1024)

#define BQ     128        // q-rows per attention CTA
#define BK     64         // keys per tile
#define SB     72         // bf16 row stride (144B: ldmatrix conflict-free)
#define SF     68         // fp32 row stride for staging
#define NSPLIT 4          // split-KV factor

// ---------------------------------------------------------------------------
// Global scratch (allocation-free rule: __device__ arrays)
// ---------------------------------------------------------------------------
__device__ __nv_bfloat16 g_qhi[BATCH * SEQ * HDIM]; // q hi [row][dim]
__device__ __nv_bfloat16 g_qlo[BATCH * SEQ * HDIM]; // q lo
__device__ __nv_bfloat16 g_whi[HDIM * DMODEL];      // Wq hi [n][k]
__device__ __nv_bfloat16 g_wlo[HDIM * DMODEL];      // Wq lo
__device__ float g_norm[BATCH * SEQ];               // |q_row|
__device__ int   g_bmax_i[BATCH];                   // max row norm (int bits)
__device__ float g_Opart[NSPLIT][BATCH * SEQ * HDIM]; // split-KV partial O
__device__ float g_lpart[NSPLIT][BATCH * SEQ];        // split-KV partial l

// ---------------------------------------------------------------------------
// helpers
// ---------------------------------------------------------------------------
__device__ __forceinline__ uint32_t smem_u32(const void* p) {
    uint32_t a;
    asm("{ .reg .u64 t; cvta.to.shared.u64 t, %1; cvt.u32.u64 %0, t; }"
        : "=r"(a) : "l"(p));
    return a;
}

// pack two floats -> bf16x2 (lo = a, hi = b), round-to-nearest-even
__device__ __forceinline__ uint32_t pack2bf(float a, float b) {
    uint32_t r;
    asm("cvt.rn.bf16x2.f32 %0, %1, %2;" : "=r"(r) : "f"(b), "f"(a));
    return r;
}

// cheap hi/lo split: 6 inst per 2 elements (proven residual trick)
__device__ __forceinline__ void split4(float4 v, uint2& hw, uint2& lw) {
    hw.x = pack2bf(v.x, v.y);
    hw.y = pack2bf(v.z, v.w);
    const float lx = v.x - __uint_as_float(hw.x << 16);
    const float ly = v.y - __uint_as_float(hw.x & 0xFFFF0000u);
    const float lz = v.z - __uint_as_float(hw.y << 16);
    const float lv = v.w - __uint_as_float(hw.y & 0xFFFF0000u);
    lw.x = pack2bf(lx, ly);
    lw.y = pack2bf(lz, lv);
}

__device__ __forceinline__ void ldmx4(uint32_t* r, uint32_t addr) {
    asm volatile("ldmatrix.sync.aligned.m8n8.x4.shared.b16 {%0,%1,%2,%3}, [%4];"
                 : "=r"(r[0]), "=r"(r[1]), "=r"(r[2]), "=r"(r[3]) : "r"(addr));
}
__device__ __forceinline__ void ldmx4t(uint32_t* r, uint32_t addr) {
    asm volatile("ldmatrix.sync.aligned.m8n8.x4.trans.shared.b16 {%0,%1,%2,%3}, [%4];"
                 : "=r"(r[0]), "=r"(r[1]), "=r"(r[2]), "=r"(r[3]) : "r"(addr));
}
__device__ __forceinline__ void mma16816(float* c, const uint32_t* a,
                                         uint32_t b0, uint32_t b1) {
    asm volatile(
        "mma.sync.aligned.m16n8k16.row.col.f32.bf16.bf16.f32 "
        "{%0,%1,%2,%3}, {%4,%5,%6,%7}, {%8,%9}, {%0,%1,%2,%3};"
        : "+f"(c[0]), "+f"(c[1]), "+f"(c[2]), "+f"(c[3])
        : "r"(a[0]), "r"(a[1]), "r"(a[2]), "r"(a[3]), "r"(b0), "r"(b1));
}
__device__ __forceinline__ void cpasync16(uint32_t dst, const void* src) {
    asm volatile("cp.async.cg.shared.global [%0], [%1], 16;"
                 :: "r"(dst), "l"(src));
}
__device__ __forceinline__ void cp_commit() {
    asm volatile("cp.async.commit_group;");
}
__device__ __forceinline__ void cp_wait0() {
    asm volatile("cp.async.wait_group 0;" ::: "memory");
}

// ---------------------------------------------------------------------------
// W split: Wq fp32 [64][1024] -> bf16 hi/lo planes (once).
// ---------------------------------------------------------------------------
__global__ __launch_bounds__(256) void wsplit_kernel(const float* __restrict__ wq)
{
    const int idx = blockIdx.x * 256 + threadIdx.x;   // float4 idx 0..16383
    float4 v = ((const float4*)wq)[idx];
    uint2 hw, lw;
    split4(v, hw, lw);
    *(uint2*)(g_whi + idx * 4) = hw;
    *(uint2*)(g_wlo + idx * 4) = lw;
}

// ---------------------------------------------------------------------------
// Projection v3: q = x · Wq^T via raw mma bf16 3-pass.
// BM=32, 256 CTAs, 256 threads (8 warps: rows (w&1)*16, cols (w>>1)*16).
// X: cp.async fp32 staging (double-buffered) -> split in SMEM.
// W: cp.async raw bf16 hi/lo tiles from pre-split g_whi/g_wlo (no split).
// Register accumulators across K=1024; 63.5KB SMEM -> 3 CTAs/SM.
// ---------------------------------------------------------------------------
#define PSTG3  (32 * SF * 4)              // 8704: one fp32 X staging buffer
#define PXF3   0                          // 2 buffers: 17408
#define PXHI3  (2 * PSTG3)                // X planes (single-buffer)
#define PXPL   (32 * SB * 2)              // 4608
#define PXLO3  (PXHI3 + PXPL)
#define PWB3   (PXLO3 + PXPL)             // 26624: W plane buffers
#define PWPL   (64 * SB * 2)              // 9216 per plane
#define PWBUF  (2 * PWPL)                 // hi+lo per buffer
#define PROJ_SMEM_BYTES (PWB3 + 2 * PWBUF)  // 63488

__global__ __launch_bounds__(256) void proj_mma_kernel(const float* __restrict__ x)
{
    extern __shared__ unsigned char psm[];
    const uint32_t smb = smem_u32(psm);

    const int tid = threadIdx.x;
    const int w   = tid >> 5;
    const int t   = tid & 31;
    const int m0  = blockIdx.x * 32;

    const __nv_bfloat16* wh = g_whi;
    const __nv_bfloat16* wl = g_wlo;

    // ---- prefetch tile 0: X fp32 + W bf16 planes into buffer 0
    #pragma unroll
    for (int u = 0; u < 2; ++u) {
        const int idx = u * 256 + tid;     // 0..511
        const int r   = idx >> 4;          // 0..31
        const int c4  = (idx & 15) << 2;
        cpasync16(smb + PXF3 + (r * SF + c4) * 4,
                  x + (size_t)(m0 + r) * DMODEL + c4);
        const int wr  = idx >> 3;          // 0..63
        const int c8  = idx & 7;
        cpasync16(smb + PWB3 + (wr * SB + c8 * 8) * 2, wh + wr * DMODEL + c8 * 8);
        cpasync16(smb + PWB3 + PWPL + (wr * SB + c8 * 8) * 2, wl + wr * DMODEL + c8 * 8);
    }
    cp_commit();

    float acc[2][4];
    #pragma unroll
    for (int j = 0; j < 2; ++j)
        #pragma unroll
        for (int e = 0; e < 4; ++e) acc[j][e] = 0.0f;

    const int arow  = (w & 1) * 16 + (t & 15);
    const int acol0 = (t >> 4) * 8;
    const int skey  = ((t >> 4) & 1) * 8 + (t & 7);
    const int scol  = ((t >> 3) & 1) * 8;
    const int nbase = (w >> 1) * 16;

    for (int kt = 0; kt < DMODEL; kt += 64) {
        cp_wait0();
        __syncthreads();
        const int buf = (kt >> 6) & 1;

        if (kt + 64 < DMODEL) {
            const uint32_t xf = smb + PXF3 + (buf ^ 1) * PSTG3;
            const uint32_t wf = smb + PWB3 + (buf ^ 1) * PWBUF;
            #pragma unroll
            for (int u = 0; u < 2; ++u) {
                const int idx = u * 256 + tid;
                const int r   = idx >> 4;
                const int c4  = (idx & 15) << 2;
                cpasync16(xf + (r * SF + c4) * 4,
                          x + (size_t)(m0 + r) * DMODEL + kt + 64 + c4);
                const int wr  = idx >> 3;
                const int c8  = idx & 7;
                cpasync16(wf + (wr * SB + c8 * 8) * 2,
                          wh + wr * DMODEL + kt + 64 + c8 * 8);
                cpasync16(wf + PWPL + (wr * SB + c8 * 8) * 2,
                          wl + wr * DMODEL + kt + 64 + c8 * 8);
            }
        }
        cp_commit();

        // split X fp32 staging -> bf16 hi/lo planes (2 float4 per thread)
        {
            const float* Xf = (const float*)(psm + PXF3 + buf * PSTG3);
            __nv_bfloat16* Xhi = (__nv_bfloat16*)(psm + PXHI3);
            __nv_bfloat16* Xlo = (__nv_bfloat16*)(psm + PXLO3);
            #pragma unroll
            for (int u = 0; u < 2; ++u) {
                const int idx = u * 256 + tid;
                const int r   = idx >> 4;
                const int c4  = (idx & 15) << 2;
                uint2 hw, lw;
                float4 v = *(const float4*)&Xf[r * SF + c4];
                split4(v, hw, lw);
                *(uint2*)(Xhi + r * SB + c4) = hw;
                *(uint2*)(Xlo + r * SB + c4) = lw;
            }
        }
        __syncthreads();

        // mma (bf16 3-pass), warp = 16 rows x 16 cols
        const uint32_t wb = smb + PWB3 + buf * PWBUF;
        #pragma unroll
        for (int ks = 0; ks < 4; ++ks) {
            uint32_t afh[4], afl[4];
            const uint32_t a = smb + PXHI3 + (arow * SB + ks * 16 + acol0) * 2;
            ldmx4(afh, a);
            ldmx4(afl, a + PXPL);
            const uint32_t boff = wb + ((nbase + skey) * SB + ks * 16 + scol) * 2;
            uint32_t bh[4], bl[4];
            ldmx4(bh, boff);
            ldmx4(bl, boff + PWPL);
            mma16816(acc[0], afh, bh[0], bh[1]);
            mma16816(acc[0], afh, bl[0], bl[1]);
            mma16816(acc[0], afl, bh[0], bh[1]);
            mma16816(acc[1], afh, bh[2], bh[3]);
            mma16816(acc[1], afh, bl[2], bl[3]);
            mma16816(acc[1], afl, bh[2], bh[3]);
        }
    }

    // ---- epilogue: stage accumulators (fp32, reuse smem)
    __syncthreads();
    float* Stg = (float*)psm;
    {
        const int r0 = (w & 1) * 16 + (t >> 2);
        const int c  = nbase + (t & 3) * 2;
        Stg[r0 * SF + c]            = acc[0][0];
        Stg[r0 * SF + c + 1]        = acc[0][1];
        Stg[(r0 + 8) * SF + c]      = acc[0][2];
        Stg[(r0 + 8) * SF + c + 1]  = acc[0][3];
        Stg[r0 * SF + c + 8]        = acc[1][0];
        Stg[r0 * SF + c + 9]        = acc[1][1];
        Stg[(r0 + 8) * SF + c + 8]  = acc[1][2];
        Stg[(r0 + 8) * SF + c + 9]  = acc[1][3];
    }
    __syncthreads();

    // split to bf16 hi/lo gmem + row norms + folded batch max
    const int rl  = tid >> 3;            // 0..31
    const int row = m0 + rl;
    const int cq  = (tid & 7) * 8;
    float n2 = 0.0f;
    #pragma unroll
    for (int j = 0; j < 2; ++j) {
        float4 v = *(const float4*)&Stg[rl * SF + cq + j * 4];
        n2 += v.x * v.x + v.y * v.y + v.z * v.z + v.w * v.w;
        uint2 hw, lw;
        split4(v, hw, lw);
        *(uint2*)(g_qhi + (size_t)row * HDIM + cq + j * 4) = hw;
        *(uint2*)(g_qlo + (size_t)row * HDIM + cq + j * 4) = lw;
    }
    n2 += __shfl_xor_sync(0xffffffffu, n2, 1);
    n2 += __shfl_xor_sync(0xffffffffu, n2, 2);
    n2 += __shfl_xor_sync(0xffffffffu, n2, 4);
    const float nrm = sqrtf(n2);
    if ((tid & 7) == 0) g_norm[row] = nrm;

    float wm = nrm;
    #pragma unroll
    for (int off = 16; off > 0; off >>= 1)
        wm = fmaxf(wm, __shfl_xor_sync(0xffffffffu, wm, off));
    if (t == 0) atomicMax(&g_bmax_i[m0 >> 11], __float_as_int(wm));
}

// ---------------------------------------------------------------------------
// FA2-style register-resident causal attention (proven R16, unchanged).
// ---------------------------------------------------------------------------
#define QREG_BYTES (BQ * SB * 2)
#define OFF_QLO    QREG_BYTES
#define OFF_K      (2 * QREG_BYTES)
#define KREG       (BK * SB * 2)
#define KBUF       (2 * KREG)
#define ATTN_SMEM_BYTES (OFF_K + 2 * KBUF)

__global__ __launch_bounds__(256) void attn_mma_kernel()
{
    extern __shared__ unsigned char smraw[];
    __nv_bfloat16* Qhi = (__nv_bfloat16*)(smraw);
    __nv_bfloat16* Qlo = (__nv_bfloat16*)(smraw + OFF_QLO);
    float*         Ostg = (float*)(smraw);        // epilogue reuse of Q region

    const uint32_t smb = smem_u32(smraw);

    const int tid   = threadIdx.x;
    const int w     = tid >> 5;
    const int t     = tid & 31;
    const int qb    = 15 - ((int)blockIdx.x >> 2);   // heavy row-blocks first
    const int split = blockIdx.x & 3;
    const int batch = blockIdx.y;
    const uint4* qh4 = (const uint4*)(g_qhi + (size_t)batch * SEQ * HDIM);
    const uint4* ql4 = (const uint4*)(g_qlo + (size_t)batch * SEQ * HDIM);

    const int nT = 2 * qb + 2;
    const int k0 = (split * nT) >> 2;
    const int k1 = ((split + 1) * nT) >> 2;

    // ---- prologue: Q tile into SMEM (raw bf16 copies)
    #pragma unroll
    for (int u = 0; u < 4; ++u) {
        const int idx = u * 256 + tid;        // uint4 idx 0..1023
        const int r   = idx >> 3;
        const int c8  = idx & 7;
        *(uint4*)(Qhi + r * SB + c8 * 8) = qh4[(qb * BQ + r) * 8 + c8];
        *(uint4*)(Qlo + r * SB + c8 * 8) = ql4[(qb * BQ + r) * 8 + c8];
    }
    // ---- prefetch first K tile into buffer 0 (only if non-empty chunk)
    if (k0 < k1) {
        const uint32_t kb = smb + OFF_K;
        #pragma unroll
        for (int u = 0; u < 2; ++u) {
            const int idx = u * 256 + tid;    // uint4 idx 0..511
            const int r   = idx >> 3;
            const int c8  = idx & 7;
            cpasync16(kb + (r * SB + c8 * 8) * 2, &qh4[(k0 * BK + r) * 8 + c8]);
            cpasync16(kb + KREG + (r * SB + c8 * 8) * 2, &ql4[(k0 * BK + r) * 8 + c8]);
        }
        cp_commit();
    }
    __syncthreads();

    // ---- hoist Q fragments (loop-invariant): 4 k-steps x (hi, lo)
    uint32_t qfh[4][4], qfl[4][4];
    {
        const int qrow  = w * 16 + (t & 15);
        const int qcol0 = (t >> 4) * 8;
        #pragma unroll
        for (int ks = 0; ks < 4; ++ks) {
            const uint32_t a = smb + (qrow * SB + ks * 16 + qcol0) * 2;
            ldmx4(qfh[ks], a);
            ldmx4(qfl[ks], a + OFF_QLO);
        }
    }

    const int r0 = qb * BQ + w * 16 + (t >> 2);   // rows r0, r0+8
    const float bm = __int_as_float(g_bmax_i[batch]);
    const float M0 = g_norm[batch * SEQ + r0]     * bm * SCALE;
    const float M1 = g_norm[batch * SEQ + r0 + 8] * bm * SCALE;

    float oc[8][4];
    #pragma unroll
    for (int j = 0; j < 8; ++j)
        #pragma unroll
        for (int e = 0; e < 4; ++e) oc[j][e] = 0.0f;
    float l0 = 0.0f, l1 = 0.0f;

    const int skey = ((t >> 4) & 1) * 8 + (t & 7);  // S (non-trans B)
    const int scol = ((t >> 3) & 1) * 8;
    const int vkey = ((t >> 3) & 1) * 8 + (t & 7);  // PV (trans B)
    const int vdim = ((t >> 4) & 1) * 8;

    for (int kt = k0; kt < k1; ++kt) {
        cp_wait0();
        __syncthreads();   // K tile kt visible to all; prev tile fully consumed

        if (kt + 1 < k1) {
            const uint32_t kb = smb + OFF_K + ((kt + 1 - k0) & 1) * KBUF;
            #pragma unroll
            for (int u = 0; u < 2; ++u) {
                const int idx = u * 256 + tid;
                const int r   = idx >> 3;
                const int c8  = idx & 7;
                cpasync16(kb + (r * SB + c8 * 8) * 2,
                          &qh4[((kt + 1) * BK + r) * 8 + c8]);
                cpasync16(kb + KREG + (r * SB + c8 * 8) * 2,
                          &ql4[((kt + 1) * BK + r) * 8 + c8]);
            }
        }
        cp_commit();

        const uint32_t kb = smb + OFF_K + ((kt - k0) & 1) * KBUF;

        // ---- S = Q · K^T (bf16 3-pass), accumulators in registers
        float sc[8][4];
        #pragma unroll
        for (int j = 0; j < 8; ++j)
            #pragma unroll
            for (int e = 0; e < 4; ++e) sc[j][e] = 0.0f;

        #pragma unroll
        for (int ks = 0; ks < 4; ++ks) {
            #pragma unroll
            for (int jp = 0; jp < 4; ++jp) {
                const uint32_t off = ((16 * jp + skey) * SB + ks * 16 + scol) * 2;
                uint32_t bh[4], bl[4];
                ldmx4(bh, kb + off);
                ldmx4(bl, kb + KREG + off);
                mma16816(sc[2 * jp],     qfh[ks], bh[0], bh[1]);
                mma16816(sc[2 * jp],     qfh[ks], bl[0], bl[1]);
                mma16816(sc[2 * jp],     qfl[ks], bh[0], bh[1]);
                mma16816(sc[2 * jp + 1], qfh[ks], bh[2], bh[3]);
                mma16816(sc[2 * jp + 1], qfh[ks], bl[2], bl[3]);
                mma16816(sc[2 * jp + 1], qfl[ks], bh[2], bh[3]);
            }
        }

        // ---- softmax in registers (static max) + causal mask; pack P hi/lo
        const bool needMask = (kt >= 2 * qb);
        uint32_t phi[4][4], plo[4][4];
        #pragma unroll
        for (int j = 0; j < 8; ++j) {
            float p0 = __expf(fmaf(sc[j][0], SCALE, -M0));
            float p1 = __expf(fmaf(sc[j][1], SCALE, -M0));
            float p2 = __expf(fmaf(sc[j][2], SCALE, -M1));
            float p3 = __expf(fmaf(sc[j][3], SCALE, -M1));
            if (needMask) {
                const int c0 = kt * BK + j * 8 + (t & 3) * 2;
                p0 = (c0     > r0    ) ? 0.0f : p0;
                p1 = (c0 + 1 > r0    ) ? 0.0f : p1;
                p2 = (c0     > r0 + 8) ? 0.0f : p2;
                p3 = (c0 + 1 > r0 + 8) ? 0.0f : p3;
            }
            l0 += p0 + p1;
            l1 += p2 + p3;
            const int kv = j >> 1;
            const uint32_t h01 = pack2bf(p0, p1);
            const uint32_t h23 = pack2bf(p2, p3);
            const uint32_t l01 = pack2bf(p0 - __uint_as_float(h01 << 16),
                                         p1 - __uint_as_float(h01 & 0xffff0000u));
            const uint32_t l23 = pack2bf(p2 - __uint_as_float(h23 << 16),
                                         p3 - __uint_as_float(h23 & 0xffff0000u));
            if ((j & 1) == 0) {
                phi[kv][0] = h01; phi[kv][1] = h23;
                plo[kv][0] = l01; plo[kv][1] = l23;
            } else {
                phi[kv][2] = h01; phi[kv][3] = h23;
                plo[kv][2] = l01; plo[kv][3] = l23;
            }
        }

        // ---- O += P · V (V == K tile via ldmatrix.trans), bf16 3-pass
        #pragma unroll
        for (int kv = 0; kv < 4; ++kv) {
            #pragma unroll
            for (int jp = 0; jp < 4; ++jp) {
                const uint32_t off = ((kv * 16 + vkey) * SB + 16 * jp + vdim) * 2;
                uint32_t vh[4], vl[4];
                ldmx4t(vh, kb + off);
                ldmx4t(vl, kb + KREG + off);
                mma16816(oc[2 * jp],     phi[kv], vh[0], vh[1]);
                mma16816(oc[2 * jp],     phi[kv], vl[0], vl[1]);
                mma16816(oc[2 * jp],     plo[kv], vh[0], vh[1]);
                mma16816(oc[2 * jp + 1], phi[kv], vh[2], vh[3]);
                mma16816(oc[2 * jp + 1], phi[kv], vl[2], vl[3]);
                mma16816(oc[2 * jp + 1], plo[kv], vh[2], vh[3]);
            }
        }
    }

    // ---- epilogue: l reduction + stage O to SMEM (Q region reuse)
    l0 += __shfl_xor_sync(0xffffffffu, l0, 1);
    l0 += __shfl_xor_sync(0xffffffffu, l0, 2);
    l1 += __shfl_xor_sync(0xffffffffu, l1, 1);
    l1 += __shfl_xor_sync(0xffffffffu, l1, 2);
    if ((t & 3) == 0) {
        g_lpart[split][batch * SEQ + r0]     = l0;
        g_lpart[split][batch * SEQ + r0 + 8] = l1;
    }

    __syncthreads();   // all warps done with loop before Q-region reuse
    {
        const int rl = w * 16 + (t >> 2);
        #pragma unroll
        for (int j = 0; j < 8; ++j) {
            const int c = j * 8 + (t & 3) * 2;
            Ostg[rl * SF + c]           = oc[j][0];
            Ostg[rl * SF + c + 1]       = oc[j][1];
            Ostg[(rl + 8) * SF + c]     = oc[j][2];
            Ostg[(rl + 8) * SF + c + 1] = oc[j][3];
        }
    }
    __syncthreads();

    // coalesced write of unnormalized partial O
    const int srow  = tid >> 1;
    const int chalf = (tid & 1) * 32;
    float* op = &g_Opart[split][((size_t)batch * SEQ + qb * BQ + srow) * HDIM];
    #pragma unroll
    for (int j = 0; j < 8; ++j) {
        const int c = chalf + j * 4;
        *(float4*)&op[c] = *(const float4*)&Ostg[srow * SF + c];
    }
}

// ---------------------------------------------------------------------------
// Combine split-KV partials: out = sum(O_s) / sum(l_s)
// ---------------------------------------------------------------------------
__global__ __launch_bounds__(256) void combine_kernel(float* __restrict__ out)
{
    const int idx = blockIdx.x * 256 + threadIdx.x;
    const int r   = idx >> 6;
    const float lsum = g_lpart[0][r] + g_lpart[1][r] +
                       g_lpart[2][r] + g_lpart[3][r];
    const float osum = g_Opart[0][idx] + g_Opart[1][idx] +
                       g_Opart[2][idx] + g_Opart[3][idx];
    out[idx] = osum / lsum;
}

extern "C" void kernel_launch(void* const* d_in, const int* in_sizes, int n_in,
                              void* d_out, int out_size)
{
    const float* x  = (const float*)d_in[0];   // [B, L, D] fp32
    const float* Wq = (const float*)d_in[1];   // [H, D] fp32
    float* out = (float*)d_out;                // [B, L, H] fp32

    cudaFuncSetAttribute(proj_mma_kernel,
                         cudaFuncAttributeMaxDynamicSharedMemorySize,
                         PROJ_SMEM_BYTES);
    cudaFuncSetAttribute(attn_mma_kernel,
                         cudaFuncAttributeMaxDynamicSharedMemorySize,
                         ATTN_SMEM_BYTES);

    wsplit_kernel<<<(HDIM * DMODEL) / (256 * 4), 256>>>(Wq);
    proj_mma_kernel<<<(BATCH * SEQ) / 32, 256, PROJ_SMEM_BYTES>>>(x);
    attn_mma_kernel<<<dim3(16 * NSPLIT, BATCH), 256, ATTN_SMEM_BYTES>>>();
    combine_kernel<<<(BATCH * SEQ * HDIM) / 256, 256>>>(out);
}